// round 6
// baseline (speedup 1.0000x reference)
#include <cuda_runtime.h>
#include <cuda_bf16.h>
#include <math.h>
#include <stdint.h>

#define BB 2048
#define DD 256
#define CC 512
#define NROW 8192
#define INVTAU (1.0f/0.07f)
#define FTOT 5767168   // 2048*(1024+1024+512+256)
#define WTOT 720896    // 256*(1024+1024+512+256)

// ---------------- scratch (no allocations allowed) ----------------
__device__ __nv_bfloat16 g_fhi[FTOT], g_flo[FTOT];
__device__ __nv_bfloat16 g_whi[WTOT], g_wlo[WTOT];
__device__ __nv_bfloat16 g_Zhi[NROW * DD], g_Zlo[NROW * DD];
__device__ __nv_bfloat16 g_Bhi[1024 * DD], g_Blo[1024 * DD]; // interleaved rows: 2c=Un_c, 2c+1=O_c
__device__ float         g_rnorm[NROW];

// warp-level bf16 MMA (proven in round 2)
#define MMA_BF16(d, a, b) asm volatile( \
    "mma.sync.aligned.m16n8k16.row.col.f32.bf16.bf16.f32 " \
    "{%0,%1,%2,%3}, {%4,%5,%6,%7}, {%8,%9}, {%0,%1,%2,%3};\n" \
    : "+f"((d)[0]), "+f"((d)[1]), "+f"((d)[2]), "+f"((d)[3]) \
    : "r"((a)[0]), "r"((a)[1]), "r"((a)[2]), "r"((a)[3]), "r"((b)[0]), "r"((b)[1]))

__device__ __forceinline__ void split2(float x, __nv_bfloat16& h, __nv_bfloat16& l) {
    h = __float2bfloat16_rn(x);
    l = __float2bfloat16_rn(x - __bfloat162float(h));
}
__device__ __forceinline__ uint32_t pack2(__nv_bfloat16 a, __nv_bfloat16 b) {
    __nv_bfloat162 t = __halves2bfloat162(a, b);
    return *(uint32_t*)&t;
}

// smem layout (dynamic):
//  [64]     params: bias|gamma|beta (768 floats)
//  [3200]   reduction scratch (512 floats)
//  [8192]   yacc: fp32 accumulator staging 128 x 257 (131584 B)
//  [139776] op tiles: 2 stages x 4 arrays x 128 x 40 bf16 (81920 B)
#define SM_PARAM 64
#define SM_RED   3200
#define SM_Y     8192
#define SM_T     139776
#define SMEM_TOTAL 221696
#define YSTR 257

// ---------------------------------------------------------------------------
// bf16 hi/lo mma.sync GEMM (CTA tile 128 rows x 256 cols, two 128-col halves,
// double-buffered kTile=32 pipeline) + fused epilogues.
//   mode 0: projections + LayerNorm + l2 factor   grid (1, 16, 4)
//   mode 1: head GEMM + softmax + finalize        grid (4, 64, 1)
// ---------------------------------------------------------------------------
__global__ void __launch_bounds__(256, 1) gemm_fused(
    int mode,
    const float* b0, const float* b1, const float* b2, const float* b3,
    const float* G0, const float* G1, const float* G2, const float* G3,
    const float* e0, const float* e1, const float* e2, const float* e3,
    const float* cls, float* out_logits, float* out_r,
    float* out_sim, float* out_contrib)
{
    extern __shared__ char smem[];
    const int tid = threadIdx.x, wid = tid >> 5, lane = tid & 31;
    float* smf   = (float*)(smem + SM_PARAM);
    float* smred = (float*)(smem + SM_RED);
    float* yacc  = (float*)(smem + SM_Y);
    __nv_bfloat16* smbuf = (__nv_bfloat16*)(smem + SM_T);

    const int md = (mode == 0) ? blockIdx.z : 0;
    if (mode == 0) {
        const float* bp = md == 0 ? b0 : md == 1 ? b1 : md == 2 ? b2 : b3;
        const float* gp = md == 0 ? G0 : md == 1 ? G1 : md == 2 ? G2 : G3;
        const float* ep = md == 0 ? e0 : md == 1 ? e1 : md == 2 ? e2 : e3;
        smf[tid] = bp[tid]; smf[256 + tid] = gp[tid]; smf[512 + tid] = ep[tid];
    }
    __syncthreads();

    // operand pointers
    const __nv_bfloat16 *Ah, *Al, *Bh, *Bl;
    int lda, ldb, K;
    const int row0 = blockIdx.y * 128;
    if (mode == 0) {
        const long foff[4] = {0, 2097152, 4194304, 5242880};
        const long woff[4] = {0, 262144, 524288, 655360};
        const int  Km[4]   = {1024, 1024, 512, 256};
        K = Km[md];
        Ah = g_fhi + foff[md] + (long)row0 * K;
        Al = g_flo + foff[md] + (long)row0 * K;
        Bh = g_whi + woff[md];
        Bl = g_wlo + woff[md];
        lda = ldb = K;
    } else {
        K = DD;
        Ah = g_Zhi + (long)row0 * DD;
        Al = g_Zlo + (long)row0 * DD;
        Bh = g_Bhi + (long)blockIdx.x * 256 * DD;
        Bl = g_Blo + (long)blockIdx.x * 256 * DD;
        lda = ldb = DD;
    }

    // ---------------- mainloop: two 128-col halves, round-2 pipeline --------
    const int wm = wid >> 2, wn = wid & 3;        // warp grid 2x4 -> 64x32 tiles
    const int g = lane >> 2, t4 = lane & 3;
    const int nkt = K >> 5;

    for (int hf = 0; hf < 2; hf++) {
        const __nv_bfloat16* Bh2 = Bh + (long)(hf * 128) * ldb;
        const __nv_bfloat16* Bl2 = Bl + (long)(hf * 128) * ldb;

        float acc[4][4][4];
#pragma unroll
        for (int im = 0; im < 4; im++)
#pragma unroll
            for (int jn = 0; jn < 4; jn++)
#pragma unroll
                for (int q = 0; q < 4; q++) acc[im][jn][q] = 0.f;

        // prologue: stage 0
        __syncthreads();
#pragma unroll
        for (int i = 0; i < 8; i++) {
            const int n = tid + (i << 8);
            const int arr = n >> 9, idx = n & 511;
            const int row = idx >> 2, ch = idx & 3;
            const __nv_bfloat16* src = arr == 0 ? Ah : arr == 1 ? Al : arr == 2 ? Bh2 : Bl2;
            const int ld = (arr < 2) ? lda : ldb;
            uint4 v = *(const uint4*)(src + (long)row * ld + (ch << 3));
            *(uint4*)(smbuf + arr * 5120 + row * 40 + (ch << 3)) = v;
        }
        __syncthreads();

        for (int kt = 0; kt < nkt; kt++) {
            uint4 pref[8];
            const bool hasNext = (kt + 1 < nkt);
            if (hasNext) {
                const int k0 = (kt + 1) << 5;
#pragma unroll
                for (int i = 0; i < 8; i++) {
                    const int n = tid + (i << 8);
                    const int arr = n >> 9, idx = n & 511;
                    const int row = idx >> 2, ch = idx & 3;
                    const __nv_bfloat16* src = arr == 0 ? Ah : arr == 1 ? Al : arr == 2 ? Bh2 : Bl2;
                    const int ld = (arr < 2) ? lda : ldb;
                    pref[i] = *(const uint4*)(src + (long)row * ld + k0 + (ch << 3));
                }
            }
            const __nv_bfloat16* sb = smbuf + (kt & 1) * 20480;
#pragma unroll
            for (int ks = 0; ks < 32; ks += 16) {
                unsigned ahi[4][4], alo[4][4], bhi[4][2], blo[4][2];
#pragma unroll
                for (int im = 0; im < 4; im++) {
                    const int r0 = wm * 64 + im * 16 + g;
                    const int o = r0 * 40 + ks + 2 * t4;
                    ahi[im][0] = *(const unsigned*)(sb + o);
                    ahi[im][1] = *(const unsigned*)(sb + o + 8 * 40);
                    ahi[im][2] = *(const unsigned*)(sb + o + 8);
                    ahi[im][3] = *(const unsigned*)(sb + o + 8 * 40 + 8);
                    alo[im][0] = *(const unsigned*)(sb + 5120 + o);
                    alo[im][1] = *(const unsigned*)(sb + 5120 + o + 8 * 40);
                    alo[im][2] = *(const unsigned*)(sb + 5120 + o + 8);
                    alo[im][3] = *(const unsigned*)(sb + 5120 + o + 8 * 40 + 8);
                }
#pragma unroll
                for (int jn = 0; jn < 4; jn++) {
                    const int n0 = wn * 32 + jn * 8 + g;
                    const int o = n0 * 40 + ks + 2 * t4;
                    bhi[jn][0] = *(const unsigned*)(sb + 10240 + o);
                    bhi[jn][1] = *(const unsigned*)(sb + 10240 + o + 8);
                    blo[jn][0] = *(const unsigned*)(sb + 15360 + o);
                    blo[jn][1] = *(const unsigned*)(sb + 15360 + o + 8);
                }
#pragma unroll
                for (int im = 0; im < 4; im++)
#pragma unroll
                    for (int jn = 0; jn < 4; jn++) {
                        MMA_BF16(acc[im][jn], ahi[im], bhi[jn]);
                        MMA_BF16(acc[im][jn], ahi[im], blo[jn]);
                        MMA_BF16(acc[im][jn], alo[im], bhi[jn]);
                    }
            }
            if (hasNext) {
                const int st = (kt + 1) & 1;
#pragma unroll
                for (int i = 0; i < 8; i++) {
                    const int n = tid + (i << 8);
                    const int arr = n >> 9, idx = n & 511;
                    const int row = idx >> 2, ch = idx & 3;
                    *(uint4*)(smbuf + st * 20480 + arr * 5120 + row * 40 + (ch << 3)) = pref[i];
                }
            }
            __syncthreads();
        }

        // stage accumulators to yacc (fragment layout -> row-major)
#pragma unroll
        for (int im = 0; im < 4; im++)
#pragma unroll
            for (int h = 0; h < 2; h++) {
                const int rl = wm * 64 + im * 16 + g + h * 8;
#pragma unroll
                for (int jn = 0; jn < 4; jn++) {
                    const int c = hf * 128 + wn * 32 + jn * 8 + 2 * t4;
                    yacc[rl * YSTR + c]     = acc[im][jn][h * 2];
                    yacc[rl * YSTR + c + 1] = acc[im][jn][h * 2 + 1];
                }
            }
    }
    __syncthreads();

    // ---------------- fused epilogue ----------------
    const int sub = wid & 3, half = wid >> 2;
    const int r = sub * 32 + lane;   // tile row; each row handled by 2 threads (col halves)

    if (mode == 0) {
        // pass 1: row sums of y = acc + bias
        float sum = 0.f, ssq = 0.f;
#pragma unroll
        for (int c4 = 0; c4 < 4; c4++) {
            const int c0 = half * 128 + c4 * 32;
#pragma unroll
            for (int j = 0; j < 32; j++) {
                const float y = yacc[r * YSTR + c0 + j] + smf[c0 + j];
                sum += y; ssq += y * y;
            }
        }
        smred[half * 128 + r] = sum;
        smred[256 + half * 128 + r] = ssq;
        __syncthreads();
        const float tot  = smred[r] + smred[128 + r];
        const float tot2 = smred[256 + r] + smred[384 + r];
        const float mu  = tot * (1.f / 256.f);
        const float var = tot2 * (1.f / 256.f) - mu * mu;
        const float rstd = rsqrtf(var + 1e-5f);
        __syncthreads();   // all reads done before smred reuse

        // pass 2: z = LN(y)*g+be -> bf16 hi/lo, accumulate ||z||^2
        float z2 = 0.f;
        const long zoff_row = ((long)(row0 + r) * 4 + md) * 256;
#pragma unroll
        for (int c4 = 0; c4 < 4; c4++) {
            const int c0 = half * 128 + c4 * 32;
            uint32_t hw[16], lw[16];
#pragma unroll
            for (int j = 0; j < 32; j += 2) {
                const float y0 = yacc[r * YSTR + c0 + j]     + smf[c0 + j];
                const float y1 = yacc[r * YSTR + c0 + j + 1] + smf[c0 + j + 1];
                const float za = (y0 - mu) * rstd * smf[256 + c0 + j]     + smf[512 + c0 + j];
                const float zb = (y1 - mu) * rstd * smf[256 + c0 + j + 1] + smf[512 + c0 + j + 1];
                z2 += za * za + zb * zb;
                __nv_bfloat16 ha, la, hb, lb;
                split2(za, ha, la); split2(zb, hb, lb);
                hw[j >> 1] = pack2(ha, hb);
                lw[j >> 1] = pack2(la, lb);
            }
            uint4* dh = (uint4*)(g_Zhi + zoff_row + c0);
            uint4* dl = (uint4*)(g_Zlo + zoff_row + c0);
#pragma unroll
            for (int q = 0; q < 4; q++) {
                dh[q] = make_uint4(hw[q * 4], hw[q * 4 + 1], hw[q * 4 + 2], hw[q * 4 + 3]);
                dl[q] = make_uint4(lw[q * 4], lw[q * 4 + 1], lw[q * 4 + 2], lw[q * 4 + 3]);
            }
        }
        smred[half * 128 + r] = z2;
        __syncthreads();
        if (tid < 128) {
            const float n2 = smred[tid] + smred[128 + tid];
            g_rnorm[((long)(row0 + tid) * 4 + md)] = 1.f / (sqrtf(n2) + 1e-6f);
        }
    } else {
        // head: cols 2j = Z.Un_c, 2j+1 = Z.O_c ; softmax over 4 adjacent lanes (m)
        const long grow = row0 + r;                 // = b*4 + m, m = lane&3
        const long bg = grow >> 2;
        const float rs = g_rnorm[grow] * INVTAU;
        const int cblk = blockIdx.x * 128;
#pragma unroll
        for (int c4 = 0; c4 < 4; c4++) {
            const int dcol = half * 128 + c4 * 32;
            const int cbase = cblk + half * 64 + c4 * 16;
            float simv[16], rv[16], ctv[16], lgv[16];
#pragma unroll
            for (int p = 0; p < 16; p++) {
                const float s = yacc[r * YSTR + dcol + 2 * p] * rs;
                const float o = yacc[r * YSTR + dcol + 2 * p + 1];
                float mx = s;
                mx = fmaxf(mx, __shfl_xor_sync(0xffffffffu, mx, 1));
                mx = fmaxf(mx, __shfl_xor_sync(0xffffffffu, mx, 2));
                const float e = __expf(s - mx);
                float tt = e + __shfl_xor_sync(0xffffffffu, e, 1);
                tt += __shfl_xor_sync(0xffffffffu, tt, 2);
                const float rr = e / tt;
                const float ct = o * rr;
                float lg = ct + __shfl_xor_sync(0xffffffffu, ct, 1);
                lg += __shfl_xor_sync(0xffffffffu, lg, 2);
                simv[p] = s; rv[p] = rr; ctv[p] = ct;
                lgv[p] = lg + __ldg(cls + cbase + p);
            }
            const long obase = grow * 512 + cbase;
            float4* ps = (float4*)(out_sim + obase);
            float4* pr = (float4*)(out_r + obase);
            float4* pc = (float4*)(out_contrib + obase);
#pragma unroll
            for (int q = 0; q < 4; q++) {
                ps[q] = make_float4(simv[q * 4], simv[q * 4 + 1], simv[q * 4 + 2], simv[q * 4 + 3]);
                pr[q] = make_float4(rv[q * 4],   rv[q * 4 + 1],   rv[q * 4 + 2],   rv[q * 4 + 3]);
                pc[q] = make_float4(ctv[q * 4],  ctv[q * 4 + 1],  ctv[q * 4 + 2],  ctv[q * 4 + 3]);
            }
            if ((lane & 3) == 0) {
                float4* pl = (float4*)(out_logits + bg * 512 + cbase);
#pragma unroll
                for (int q = 0; q < 4; q++)
                    pl[q] = make_float4(lgv[q * 4], lgv[q * 4 + 1], lgv[q * 4 + 2], lgv[q * 4 + 3]);
            }
        }
    }
}

// ---------------------------------------------------------------------------
// fp32 -> bf16 hi/lo conversion for f_* and W_*
// ---------------------------------------------------------------------------
__global__ void __launch_bounds__(256) cvt_fw(
    const float* f0, const float* f1, const float* f2, const float* f3,
    const float* w0, const float* w1, const float* w2, const float* w3)
{
    const int cum[8] = {2048, 4096, 5120, 5632, 5888, 6144, 6272, 6336};
    int blk = blockIdx.x, seg = 0;
    while (blk >= cum[seg]) seg++;
    int lb = blk - (seg ? cum[seg - 1] : 0);
    const float* src;
    __nv_bfloat16 *hi, *lo;
    switch (seg) {
        case 0: src = f0; hi = g_fhi;           lo = g_flo;           break;
        case 1: src = f1; hi = g_fhi + 2097152; lo = g_flo + 2097152; break;
        case 2: src = f2; hi = g_fhi + 4194304; lo = g_flo + 4194304; break;
        case 3: src = f3; hi = g_fhi + 5242880; lo = g_flo + 5242880; break;
        case 4: src = w0; hi = g_whi;           lo = g_wlo;           break;
        case 5: src = w1; hi = g_whi + 262144;  lo = g_wlo + 262144;  break;
        case 6: src = w2; hi = g_whi + 524288;  lo = g_wlo + 524288;  break;
        default:src = w3; hi = g_whi + 655360;  lo = g_wlo + 655360;  break;
    }
    long base = (long)lb * 1024 + threadIdx.x * 4;
    float4 v = *(const float4*)(src + base);
    __nv_bfloat16 h0, h1, h2, h3, l0, l1, l2, l3;
    split2(v.x, h0, l0); split2(v.y, h1, l1);
    split2(v.z, h2, l2); split2(v.w, h3, l3);
    *(__nv_bfloat162*)(hi + base)     = __halves2bfloat162(h0, h1);
    *(__nv_bfloat162*)(hi + base + 2) = __halves2bfloat162(h2, h3);
    *(__nv_bfloat162*)(lo + base)     = __halves2bfloat162(l0, l1);
    *(__nv_bfloat162*)(lo + base + 2) = __halves2bfloat162(l2, l3);
}

// ---------------------------------------------------------------------------
// Bcat rows interleaved: row 2c = l2norm(U)_c, row 2c+1 = O_c  -> bf16 hi/lo
// ---------------------------------------------------------------------------
__global__ void __launch_bounds__(256) normcat_kernel(const float* __restrict__ U,
                                                      const float* __restrict__ O)
{
    const int rr = blockIdx.x, t = threadIdx.x;
    const int c = rr >> 1, kind = rr & 1;
    __shared__ float ws[8];
    float v;
    if (kind == 0) {
        float u = U[(long)c * DD + t];
        float q = u * u;
#pragma unroll
        for (int o = 16; o > 0; o >>= 1) q += __shfl_xor_sync(0xffffffffu, q, o);
        if ((t & 31) == 0) ws[t >> 5] = q;
        __syncthreads();
        float n2 = 0.f;
#pragma unroll
        for (int i = 0; i < 8; i++) n2 += ws[i];
        v = u / (sqrtf(n2) + 1e-6f);
    } else {
        v = O[(long)c * DD + t];
    }
    __nv_bfloat16 h, l; split2(v, h, l);
    g_Bhi[(long)rr * DD + t] = h;
    g_Blo[(long)rr * DD + t] = l;
}

// ---------------------------------------------------------------------------
extern "C" void kernel_launch(void* const* d_in, const int* in_sizes, int n_in,
                              void* d_out, int out_size)
{
    const float *f[4], *W[4], *bi[4], *ga[4], *be[4];
    if (in_sizes[1] == 256 * 1024) {   // dict order: (f,W,b,g,be) per modality
        for (int m = 0; m < 4; m++) {
            f[m]  = (const float*)d_in[m * 5 + 0];
            W[m]  = (const float*)d_in[m * 5 + 1];
            bi[m] = (const float*)d_in[m * 5 + 2];
            ga[m] = (const float*)d_in[m * 5 + 3];
            be[m] = (const float*)d_in[m * 5 + 4];
        }
    } else {                            // signature order
        for (int m = 0; m < 4; m++) f[m] = (const float*)d_in[m];
        for (int m = 0; m < 4; m++) {
            W[m]  = (const float*)d_in[4 + m * 4 + 0];
            bi[m] = (const float*)d_in[4 + m * 4 + 1];
            ga[m] = (const float*)d_in[4 + m * 4 + 2];
            be[m] = (const float*)d_in[4 + m * 4 + 3];
        }
    }
    const float* U   = (const float*)d_in[20];
    const float* O   = (const float*)d_in[21];
    const float* cls = (const float*)d_in[22];

    float* out         = (float*)d_out;
    float* out_logits  = out;
    float* out_r       = out + (long)BB * CC;
    float* out_sim     = out_r + (long)NROW * CC;
    float* out_contrib = out_sim + (long)NROW * CC;

    cudaFuncSetAttribute(gemm_fused, cudaFuncAttributeMaxDynamicSharedMemorySize, SMEM_TOTAL);

    cvt_fw<<<6336, 256>>>(f[0], f[1], f[2], f[3], W[0], W[1], W[2], W[3]);
    normcat_kernel<<<1024, 256>>>(U, O);

    // projections + fused LayerNorm/l2 (Z emitted as bf16 hi/lo, rnorm filled)
    gemm_fused<<<dim3(1, 16, 4), 256, SMEM_TOTAL>>>(
        0, bi[0], bi[1], bi[2], bi[3], ga[0], ga[1], ga[2], ga[3],
        be[0], be[1], be[2], be[3], nullptr, nullptr, nullptr, nullptr, nullptr);

    // head GEMM + fused softmax/finalize (writes all four outputs)
    gemm_fused<<<dim3(4, 64, 1), 256, SMEM_TOTAL>>>(
        1, nullptr, nullptr, nullptr, nullptr, nullptr, nullptr, nullptr, nullptr,
        nullptr, nullptr, nullptr, nullptr, cls, out_logits, out_r, out_sim, out_contrib);
}

// round 7
// speedup vs baseline: 1.4174x; 1.4174x over previous
#include <cuda_runtime.h>
#include <cuda_bf16.h>
#include <math.h>
#include <stdint.h>

#define BB 2048
#define DD 256
#define CC 512
#define NROW 8192
#define INVTAU (1.0f/0.07f)
#define FTOT 5767168   // 2048*(1024+1024+512+256)
#define WTOT 720896    // 256*(1024+1024+512+256)

// ---------------- scratch (no allocations allowed) ----------------
__device__ __nv_bfloat16 g_fhi[FTOT], g_flo[FTOT];
__device__ __nv_bfloat16 g_whi[WTOT], g_wlo[WTOT];
__device__ __nv_bfloat16 g_Zhi[NROW * DD], g_Zlo[NROW * DD];
__device__ __nv_bfloat16 g_Bhi[1024 * DD], g_Blo[1024 * DD]; // interleaved rows: 2c=Un_c, 2c+1=O_c
__device__ float         g_rnorm[NROW];

#define MMA_BF16(d, a, b) asm volatile( \
    "mma.sync.aligned.m16n8k16.row.col.f32.bf16.bf16.f32 " \
    "{%0,%1,%2,%3}, {%4,%5,%6,%7}, {%8,%9}, {%0,%1,%2,%3};\n" \
    : "+f"((d)[0]), "+f"((d)[1]), "+f"((d)[2]), "+f"((d)[3]) \
    : "r"((a)[0]), "r"((a)[1]), "r"((a)[2]), "r"((a)[3]), "r"((b)[0]), "r"((b)[1]))

#define CP16(dst, src) asm volatile("cp.async.cg.shared.global [%0], [%1], 16;" :: "r"(dst), "l"(src))
#define CP_COMMIT()    asm volatile("cp.async.commit_group;" ::: "memory")
#define CP_WAIT0()     asm volatile("cp.async.wait_group 0;" ::: "memory")
#define CP_WAIT1()     asm volatile("cp.async.wait_group 1;" ::: "memory")

__device__ __forceinline__ uint32_t smem_u32(const void* p) {
    uint32_t a;
    asm("{ .reg .u64 t; cvta.to.shared.u64 t, %1; cvt.u32.u64 %0, t; }" : "=r"(a) : "l"(p));
    return a;
}
__device__ __forceinline__ void split2(float x, __nv_bfloat16& h, __nv_bfloat16& l) {
    h = __float2bfloat16_rn(x);
    l = __float2bfloat16_rn(x - __bfloat162float(h));
}
__device__ __forceinline__ uint32_t pack2(__nv_bfloat16 a, __nv_bfloat16 b) {
    __nv_bfloat162 t = __halves2bfloat162(a, b);
    return *(uint32_t*)&t;
}

// smem layout (dynamic):
//  [0]     params: bias|gamma|beta (768 f)           3072 B
//  [3072]  smred: 8 warps x 64 rows x 2 (sum,ssq)    4096 B
//  [7168]  stats: 64 rows x 2 (mu,rstd)               512 B
//  [7680]  tiles: 2 stages x 51200 B               102400 B
//          per stage: Ahi 5120 | Alo 5120 | Bhi 20480 | Blo 20480
//          (rows x 40-bf16 stride; 32 bf16 data per row)
#define SM_PARAM 0
#define SM_RED   3072
#define SM_STAT  7168
#define SM_T     7680
#define STAGE_B  51200
#define SMEM_TOTAL (SM_T + 2 * STAGE_B)   // 110080

// issue cp.async for one K32 stage: A 64 rows, B 256 rows, hi+lo
__device__ __forceinline__ void load_stage_async(
    uint32_t tile_sm, const __nv_bfloat16* Ah, const __nv_bfloat16* Al,
    const __nv_bfloat16* Bh, const __nv_bfloat16* Bl,
    int lda, int ldb, int k0, int tid)
{
    {   // A: 2 arrays x 256 uint4 (tid 0..511)
        const int a = tid >> 8, idx = tid & 255;
        const int row = idx >> 2, ch = idx & 3;
        const __nv_bfloat16* src = a ? Al : Ah;
        const char* gsrc = (const char*)(src + (long)row * lda + k0 + (ch << 3));
        CP16(tile_sm + a * 5120 + row * 80 + (ch << 4), gsrc);
    }
#pragma unroll
    for (int i = 0; i < 4; i++) {   // B: 2 arrays x 1024 uint4
        const int m = tid + (i << 9);
        const int a = m >> 10, idx = m & 1023;
        const int row = idx >> 2, ch = idx & 3;
        const __nv_bfloat16* src = a ? Bl : Bh;
        const char* gsrc = (const char*)(src + (long)row * ldb + k0 + (ch << 3));
        CP16(tile_sm + 10240 + a * 20480 + row * 80 + (ch << 4), gsrc);
    }
    CP_COMMIT();
}

// ---------------------------------------------------------------------------
// CTA tile 64 rows x 256 cols, 512 threads, warp grid 2x8 (warp tile 32x32).
//   mode 0: projections + fused LayerNorm/l2   grid (1, 32, 4)
//   mode 1: head GEMM + fused softmax/finalize grid (4, 128, 1)
// ---------------------------------------------------------------------------
__global__ void __launch_bounds__(512, 1) gemm_fused(
    int mode,
    const float* b0, const float* b1, const float* b2, const float* b3,
    const float* G0, const float* G1, const float* G2, const float* G3,
    const float* e0, const float* e1, const float* e2, const float* e3,
    const float* cls, float* out_logits, float* out_r,
    float* out_sim, float* out_contrib)
{
    extern __shared__ char smem[];
    const uint32_t sbase = smem_u32(smem);
    const int tid = threadIdx.x, wid = tid >> 5, lane = tid & 31;
    float* smf   = (float*)(smem + SM_PARAM);
    float* smred = (float*)(smem + SM_RED);
    float* smst  = (float*)(smem + SM_STAT);
    __nv_bfloat16* smtile = (__nv_bfloat16*)(smem + SM_T);

    const int md = (mode == 0) ? blockIdx.z : 0;
    if (mode == 0 && tid < 256) {
        const float* bp = md == 0 ? b0 : md == 1 ? b1 : md == 2 ? b2 : b3;
        const float* gp = md == 0 ? G0 : md == 1 ? G1 : md == 2 ? G2 : G3;
        const float* ep = md == 0 ? e0 : md == 1 ? e1 : md == 2 ? e2 : e3;
        smf[tid] = bp[tid]; smf[256 + tid] = gp[tid]; smf[512 + tid] = ep[tid];
    }
    __syncthreads();

    // operand pointers
    const __nv_bfloat16 *Ah, *Al, *Bh, *Bl;
    int lda, ldb, K;
    const int row0 = blockIdx.y * 64;
    if (mode == 0) {
        const long foff[4] = {0, 2097152, 4194304, 5242880};
        const long woff[4] = {0, 262144, 524288, 655360};
        const int  Km[4]   = {1024, 1024, 512, 256};
        K = Km[md];
        Ah = g_fhi + foff[md] + (long)row0 * K;
        Al = g_flo + foff[md] + (long)row0 * K;
        Bh = g_whi + woff[md];
        Bl = g_wlo + woff[md];
        lda = ldb = K;
    } else {
        K = DD;
        Ah = g_Zhi + (long)row0 * DD;
        Al = g_Zlo + (long)row0 * DD;
        Bh = g_Bhi + (long)blockIdx.x * 256 * DD;
        Bl = g_Blo + (long)blockIdx.x * 256 * DD;
        lda = ldb = DD;
    }
    const int nkt = K >> 5;

    const int wm = wid >> 3, wn = wid & 7;    // 2 row-warps x 8 col-warps
    const int g = lane >> 2, t4 = lane & 3;

    float acc[2][4][4];
#pragma unroll
    for (int im = 0; im < 2; im++)
#pragma unroll
        for (int jn = 0; jn < 4; jn++)
#pragma unroll
            for (int q = 0; q < 4; q++) acc[im][jn][q] = 0.f;

    // ---------------- cp.async double-buffered mainloop ----------------
    load_stage_async(sbase + SM_T, Ah, Al, Bh, Bl, lda, ldb, 0, tid);
    for (int kt = 0; kt < nkt; kt++) {
        const bool hasNext = (kt + 1 < nkt);
        if (hasNext)
            load_stage_async(sbase + SM_T + ((kt + 1) & 1) * STAGE_B,
                             Ah, Al, Bh, Bl, lda, ldb, (kt + 1) << 5, tid);
        if (hasNext) CP_WAIT1(); else CP_WAIT0();
        __syncthreads();

        const __nv_bfloat16* sb = smtile + (kt & 1) * (STAGE_B / 2);
        // element offsets: Ahi 0, Alo 2560, Bhi 5120, Blo 15360 (stride 40)
#pragma unroll
        for (int ks = 0; ks < 32; ks += 16) {
            unsigned ahi[2][4], alo[2][4], bhi[4][2], blo[4][2];
#pragma unroll
            for (int im = 0; im < 2; im++) {
                const int r0 = wm * 32 + im * 16 + g;
                const int o = r0 * 40 + ks + 2 * t4;
                ahi[im][0] = *(const unsigned*)(sb + o);
                ahi[im][1] = *(const unsigned*)(sb + o + 8 * 40);
                ahi[im][2] = *(const unsigned*)(sb + o + 8);
                ahi[im][3] = *(const unsigned*)(sb + o + 8 * 40 + 8);
                alo[im][0] = *(const unsigned*)(sb + 2560 + o);
                alo[im][1] = *(const unsigned*)(sb + 2560 + o + 8 * 40);
                alo[im][2] = *(const unsigned*)(sb + 2560 + o + 8);
                alo[im][3] = *(const unsigned*)(sb + 2560 + o + 8 * 40 + 8);
            }
#pragma unroll
            for (int jn = 0; jn < 4; jn++) {
                const int n0 = wn * 32 + jn * 8 + g;
                const int o = n0 * 40 + ks + 2 * t4;
                bhi[jn][0] = *(const unsigned*)(sb + 5120 + o);
                bhi[jn][1] = *(const unsigned*)(sb + 5120 + o + 8);
                blo[jn][0] = *(const unsigned*)(sb + 15360 + o);
                blo[jn][1] = *(const unsigned*)(sb + 15360 + o + 8);
            }
#pragma unroll
            for (int im = 0; im < 2; im++)
#pragma unroll
                for (int jn = 0; jn < 4; jn++) {
                    MMA_BF16(acc[im][jn], ahi[im], bhi[jn]);
                    MMA_BF16(acc[im][jn], ahi[im], blo[jn]);
                    MMA_BF16(acc[im][jn], alo[im], bhi[jn]);
                }
        }
        __syncthreads();
    }

    // ---------------- fused register epilogue ----------------
    // thread owns rows: wm*32 + im*16 + g + h*8  (im,h in {0,1})
    //          cols:    wn*32 + jn*8 + 2*t4 + e  (jn in 0..3, e in {0,1})
    if (mode == 0) {
        // pass 1: y = acc + bias; per-row partial sums
        float sums[2][2] = {{0, 0}, {0, 0}}, ssqs[2][2] = {{0, 0}, {0, 0}};
#pragma unroll
        for (int im = 0; im < 2; im++)
#pragma unroll
            for (int jn = 0; jn < 4; jn++)
#pragma unroll
                for (int h = 0; h < 2; h++)
#pragma unroll
                    for (int e = 0; e < 2; e++) {
                        const int col = wn * 32 + jn * 8 + 2 * t4 + e;
                        const float y = acc[im][jn][h * 2 + e] + smf[col];
                        acc[im][jn][h * 2 + e] = y;
                        sums[im][h] += y; ssqs[im][h] += y * y;
                    }
#pragma unroll
        for (int im = 0; im < 2; im++)
#pragma unroll
            for (int h = 0; h < 2; h++) {
                sums[im][h] += __shfl_xor_sync(0xffffffffu, sums[im][h], 1);
                sums[im][h] += __shfl_xor_sync(0xffffffffu, sums[im][h], 2);
                ssqs[im][h] += __shfl_xor_sync(0xffffffffu, ssqs[im][h], 1);
                ssqs[im][h] += __shfl_xor_sync(0xffffffffu, ssqs[im][h], 2);
            }
        if (t4 == 0) {
#pragma unroll
            for (int im = 0; im < 2; im++)
#pragma unroll
                for (int h = 0; h < 2; h++) {
                    const int row = wm * 32 + im * 16 + g + h * 8;
                    smred[wn * 128 + row * 2]     = sums[im][h];
                    smred[wn * 128 + row * 2 + 1] = ssqs[im][h];
                }
        }
        __syncthreads();
        if (tid < 64) {
            float s = 0.f, q = 0.f;
#pragma unroll
            for (int w = 0; w < 8; w++) {
                s += smred[w * 128 + tid * 2];
                q += smred[w * 128 + tid * 2 + 1];
            }
            const float mu = s * (1.f / 256.f);
            const float var = q * (1.f / 256.f) - mu * mu;
            smst[tid * 2]     = mu;
            smst[tid * 2 + 1] = rsqrtf(var + 1e-5f);
        }
        __syncthreads();

        // pass 2: z = LN(y)*gamma+beta -> bf16 hi/lo; accumulate ||z||^2
        float z2[2][2] = {{0, 0}, {0, 0}};
#pragma unroll
        for (int im = 0; im < 2; im++)
#pragma unroll
            for (int h = 0; h < 2; h++) {
                const int row = wm * 32 + im * 16 + g + h * 8;
                const float mu = smst[row * 2], rstd = smst[row * 2 + 1];
                const long zrow = ((long)(row0 + row) * 4 + md) * 256;
#pragma unroll
                for (int jn = 0; jn < 4; jn++) {
                    const int c0 = wn * 32 + jn * 8 + 2 * t4;
                    const float z0 = (acc[im][jn][h * 2]     - mu) * rstd * smf[256 + c0]     + smf[512 + c0];
                    const float z1 = (acc[im][jn][h * 2 + 1] - mu) * rstd * smf[256 + c0 + 1] + smf[512 + c0 + 1];
                    z2[im][h] += z0 * z0 + z1 * z1;
                    __nv_bfloat16 h0, l0, h1, l1;
                    split2(z0, h0, l0); split2(z1, h1, l1);
                    *(uint32_t*)(g_Zhi + zrow + c0) = pack2(h0, h1);
                    *(uint32_t*)(g_Zlo + zrow + c0) = pack2(l0, l1);
                }
            }
#pragma unroll
        for (int im = 0; im < 2; im++)
#pragma unroll
            for (int h = 0; h < 2; h++) {
                z2[im][h] += __shfl_xor_sync(0xffffffffu, z2[im][h], 1);
                z2[im][h] += __shfl_xor_sync(0xffffffffu, z2[im][h], 2);
            }
        __syncthreads();   // smred reads above are done; safe to reuse
        if (t4 == 0) {
#pragma unroll
            for (int im = 0; im < 2; im++)
#pragma unroll
                for (int h = 0; h < 2; h++) {
                    const int row = wm * 32 + im * 16 + g + h * 8;
                    smred[wn * 128 + row * 2] = z2[im][h];
                }
        }
        __syncthreads();
        if (tid < 64) {
            float n2 = 0.f;
#pragma unroll
            for (int w = 0; w < 8; w++) n2 += smred[w * 128 + tid * 2];
            g_rnorm[((long)(row0 + tid) * 4 + md)] = 1.f / (sqrtf(n2) + 1e-6f);
        }
    } else {
        // head: fragment cols pair (2j, 2j+1) = (Z.Un_cg, Z.O_cg).
        // softmax over m: rows b*4+m land on lanes l, l^4, l^8, l^12.
        float rs[2][2];
#pragma unroll
        for (int im = 0; im < 2; im++)
#pragma unroll
            for (int h = 0; h < 2; h++)
                rs[im][h] = g_rnorm[row0 + wm * 32 + im * 16 + g + h * 8] * INVTAU;
#pragma unroll
        for (int im = 0; im < 2; im++)
#pragma unroll
            for (int jn = 0; jn < 4; jn++)
#pragma unroll
                for (int h = 0; h < 2; h++) {
                    const long grow = row0 + wm * 32 + im * 16 + g + h * 8;
                    const float s = acc[im][jn][h * 2] * rs[im][h];
                    const float o = acc[im][jn][h * 2 + 1];
                    float mx = s;
                    mx = fmaxf(mx, __shfl_xor_sync(0xffffffffu, mx, 4));
                    mx = fmaxf(mx, __shfl_xor_sync(0xffffffffu, mx, 8));
                    const float e = __expf(s - mx);
                    float tt = e + __shfl_xor_sync(0xffffffffu, e, 4);
                    tt += __shfl_xor_sync(0xffffffffu, tt, 8);
                    const float rr = e / tt;
                    const float ct = o * rr;
                    float lg = ct + __shfl_xor_sync(0xffffffffu, ct, 4);
                    lg += __shfl_xor_sync(0xffffffffu, lg, 8);
                    const int cg = blockIdx.x * 128 + wn * 16 + jn * 4 + t4;
                    const long obase = grow * 512 + cg;
                    out_sim[obase]     = s;
                    out_r[obase]       = rr;
                    out_contrib[obase] = ct;
                    if ((grow & 3) == 0)
                        out_logits[(grow >> 2) * 512 + cg] = lg + __ldg(cls + cg);
                }
    }
}

// ---------------------------------------------------------------------------
// fp32 -> bf16 hi/lo conversion for f_* and W_*
// ---------------------------------------------------------------------------
__global__ void __launch_bounds__(256) cvt_fw(
    const float* f0, const float* f1, const float* f2, const float* f3,
    const float* w0, const float* w1, const float* w2, const float* w3)
{
    const int cum[8] = {2048, 4096, 5120, 5632, 5888, 6144, 6272, 6336};
    int blk = blockIdx.x, seg = 0;
    while (blk >= cum[seg]) seg++;
    int lb = blk - (seg ? cum[seg - 1] : 0);
    const float* src;
    __nv_bfloat16 *hi, *lo;
    switch (seg) {
        case 0: src = f0; hi = g_fhi;           lo = g_flo;           break;
        case 1: src = f1; hi = g_fhi + 2097152; lo = g_flo + 2097152; break;
        case 2: src = f2; hi = g_fhi + 4194304; lo = g_flo + 4194304; break;
        case 3: src = f3; hi = g_fhi + 5242880; lo = g_flo + 5242880; break;
        case 4: src = w0; hi = g_whi;           lo = g_wlo;           break;
        case 5: src = w1; hi = g_whi + 262144;  lo = g_wlo + 262144;  break;
        case 6: src = w2; hi = g_whi + 524288;  lo = g_wlo + 524288;  break;
        default:src = w3; hi = g_whi + 655360;  lo = g_wlo + 655360;  break;
    }
    long base = (long)lb * 1024 + threadIdx.x * 4;
    float4 v = *(const float4*)(src + base);
    __nv_bfloat16 h0, h1, h2, h3, l0, l1, l2, l3;
    split2(v.x, h0, l0); split2(v.y, h1, l1);
    split2(v.z, h2, l2); split2(v.w, h3, l3);
    *(__nv_bfloat162*)(hi + base)     = __halves2bfloat162(h0, h1);
    *(__nv_bfloat162*)(hi + base + 2) = __halves2bfloat162(h2, h3);
    *(__nv_bfloat162*)(lo + base)     = __halves2bfloat162(l0, l1);
    *(__nv_bfloat162*)(lo + base + 2) = __halves2bfloat162(l2, l3);
}

// ---------------------------------------------------------------------------
// Bcat rows interleaved: row 2c = l2norm(U)_c, row 2c+1 = O_c  -> bf16 hi/lo
// ---------------------------------------------------------------------------
__global__ void __launch_bounds__(256) normcat_kernel(const float* __restrict__ U,
                                                      const float* __restrict__ O)
{
    const int rr = blockIdx.x, t = threadIdx.x;
    const int c = rr >> 1, kind = rr & 1;
    __shared__ float ws[8];
    float v;
    if (kind == 0) {
        float u = U[(long)c * DD + t];
        float q = u * u;
#pragma unroll
        for (int o = 16; o > 0; o >>= 1) q += __shfl_xor_sync(0xffffffffu, q, o);
        if ((t & 31) == 0) ws[t >> 5] = q;
        __syncthreads();
        float n2 = 0.f;
#pragma unroll
        for (int i = 0; i < 8; i++) n2 += ws[i];
        v = u / (sqrtf(n2) + 1e-6f);
    } else {
        v = O[(long)c * DD + t];
    }
    __nv_bfloat16 h, l; split2(v, h, l);
    g_Bhi[(long)rr * DD + t] = h;
    g_Blo[(long)rr * DD + t] = l;
}

// ---------------------------------------------------------------------------
extern "C" void kernel_launch(void* const* d_in, const int* in_sizes, int n_in,
                              void* d_out, int out_size)
{
    const float *f[4], *W[4], *bi[4], *ga[4], *be[4];
    if (in_sizes[1] == 256 * 1024) {   // dict order: (f,W,b,g,be) per modality
        for (int m = 0; m < 4; m++) {
            f[m]  = (const float*)d_in[m * 5 + 0];
            W[m]  = (const float*)d_in[m * 5 + 1];
            bi[m] = (const float*)d_in[m * 5 + 2];
            ga[m] = (const float*)d_in[m * 5 + 3];
            be[m] = (const float*)d_in[m * 5 + 4];
        }
    } else {                            // signature order
        for (int m = 0; m < 4; m++) f[m] = (const float*)d_in[m];
        for (int m = 0; m < 4; m++) {
            W[m]  = (const float*)d_in[4 + m * 4 + 0];
            bi[m] = (const float*)d_in[4 + m * 4 + 1];
            ga[m] = (const float*)d_in[4 + m * 4 + 2];
            be[m] = (const float*)d_in[4 + m * 4 + 3];
        }
    }
    const float* U   = (const float*)d_in[20];
    const float* O   = (const float*)d_in[21];
    const float* cls = (const float*)d_in[22];

    float* out         = (float*)d_out;
    float* out_logits  = out;
    float* out_r       = out + (long)BB * CC;
    float* out_sim     = out_r + (long)NROW * CC;
    float* out_contrib = out_sim + (long)NROW * CC;

    cudaFuncSetAttribute(gemm_fused, cudaFuncAttributeMaxDynamicSharedMemorySize, SMEM_TOTAL);

    cvt_fw<<<6336, 256>>>(f[0], f[1], f[2], f[3], W[0], W[1], W[2], W[3]);
    normcat_kernel<<<1024, 256>>>(U, O);

    // projections + fused LayerNorm/l2 (Z emitted as bf16 hi/lo, rnorm filled)
    gemm_fused<<<dim3(1, 32, 4), 512, SMEM_TOTAL>>>(
        0, bi[0], bi[1], bi[2], bi[3], ga[0], ga[1], ga[2], ga[3],
        be[0], be[1], be[2], be[3], nullptr, nullptr, nullptr, nullptr, nullptr);

    // head GEMM + fused softmax/finalize (writes all four outputs)
    gemm_fused<<<dim3(4, 128, 1), 512, SMEM_TOTAL>>>(
        1, nullptr, nullptr, nullptr, nullptr, nullptr, nullptr, nullptr, nullptr,
        nullptr, nullptr, nullptr, nullptr, cls, out_logits, out_r, out_sim, out_contrib);
}

// round 8
// speedup vs baseline: 1.4428x; 1.0179x over previous
#include <cuda_runtime.h>
#include <cuda_bf16.h>
#include <math.h>
#include <stdint.h>

#define BB 2048
#define DD 256
#define CC 512
#define NROW 8192
#define INVTAU (1.0f/0.07f)
#define FTOT 5767168   // 2048*(1024+1024+512+256)
#define WTOT 720896    // 256*(1024+1024+512+256)

// ---------------- scratch (no allocations allowed) ----------------
__device__ __nv_bfloat16 g_fhi[FTOT], g_flo[FTOT];
__device__ __nv_bfloat16 g_whi[WTOT], g_wlo[WTOT];
__device__ __nv_bfloat16 g_Zhi[NROW * DD], g_Zlo[NROW * DD];
__device__ __nv_bfloat16 g_Bhi[1024 * DD], g_Blo[1024 * DD]; // interleaved rows: 2c=Un_c, 2c+1=O_c
__device__ float         g_rnorm[NROW];

#define MMA_BF16(d, a, b) asm volatile( \
    "mma.sync.aligned.m16n8k16.row.col.f32.bf16.bf16.f32 " \
    "{%0,%1,%2,%3}, {%4,%5,%6,%7}, {%8,%9}, {%0,%1,%2,%3};\n" \
    : "+f"((d)[0]), "+f"((d)[1]), "+f"((d)[2]), "+f"((d)[3]) \
    : "r"((a)[0]), "r"((a)[1]), "r"((a)[2]), "r"((a)[3]), "r"((b)[0]), "r"((b)[1]))

#define LDM4(r, addr) asm volatile( \
    "ldmatrix.sync.aligned.m8n8.x4.shared.b16 {%0,%1,%2,%3}, [%4];" \
    : "=r"((r)[0]), "=r"((r)[1]), "=r"((r)[2]), "=r"((r)[3]) : "r"(addr))

#define CP16(dst, src) asm volatile("cp.async.cg.shared.global [%0], [%1], 16;" :: "r"(dst), "l"(src))
#define CP_COMMIT()    asm volatile("cp.async.commit_group;" ::: "memory")
#define CP_WAIT0()     asm volatile("cp.async.wait_group 0;" ::: "memory")
#define CP_WAIT1()     asm volatile("cp.async.wait_group 1;" ::: "memory")

__device__ __forceinline__ uint32_t smem_u32(const void* p) {
    uint32_t a;
    asm("{ .reg .u64 t; cvta.to.shared.u64 t, %1; cvt.u32.u64 %0, t; }" : "=r"(a) : "l"(p));
    return a;
}
__device__ __forceinline__ void split2(float x, __nv_bfloat16& h, __nv_bfloat16& l) {
    h = __float2bfloat16_rn(x);
    l = __float2bfloat16_rn(x - __bfloat162float(h));
}
__device__ __forceinline__ uint32_t pack2(__nv_bfloat16 a, __nv_bfloat16 b) {
    __nv_bfloat162 t = __halves2bfloat162(a, b);
    return *(uint32_t*)&t;
}

// smem layout (dynamic):
//  [0]     params: bias|gamma|beta (768 f)           3072 B
//  [3072]  smred: 4 warp-cols x 64 rows x 2          2048 B
//  [5632]  stats: 64 rows x 2 (mu,rstd)               512 B
//  [7680]  tiles: 2 stages x 51200 B               102400 B
//          per stage (element offsets, stride 40 bf16 = 80 B/row):
//          Ahi 0 | Alo 2560 | Bhi 5120 | Blo 15360
#define SM_PARAM 0
#define SM_RED   3072
#define SM_STAT  5632
#define SM_T     7680
#define STAGE_B  51200
#define SMEM_TOTAL (SM_T + 2 * STAGE_B)   // 110080

// issue cp.async for one K32 stage: A 64 rows, B 256 rows, hi+lo
__device__ __forceinline__ void load_stage_async(
    uint32_t tile_sm, const __nv_bfloat16* Ah, const __nv_bfloat16* Al,
    const __nv_bfloat16* Bh, const __nv_bfloat16* Bl,
    int lda, int ldb, int k0, int tid)
{
    {   // A: 2 arrays x 256 uint4 (tid 0..511)
        const int a = tid >> 8, idx = tid & 255;
        const int row = idx >> 2, ch = idx & 3;
        const __nv_bfloat16* src = a ? Al : Ah;
        const char* gsrc = (const char*)(src + (long)row * lda + k0 + (ch << 3));
        CP16(tile_sm + a * 5120 + row * 80 + (ch << 4), gsrc);
    }
#pragma unroll
    for (int i = 0; i < 4; i++) {   // B: 2 arrays x 1024 uint4
        const int m = tid + (i << 9);
        const int a = m >> 10, idx = m & 1023;
        const int row = idx >> 2, ch = idx & 3;
        const __nv_bfloat16* src = a ? Bl : Bh;
        const char* gsrc = (const char*)(src + (long)row * ldb + k0 + (ch << 3));
        CP16(tile_sm + 10240 + a * 20480 + row * 80 + (ch << 4), gsrc);
    }
    CP_COMMIT();
}

// ---------------------------------------------------------------------------
// CTA tile 64 rows x 256 cols, 512 threads, warp grid 4x4 (warp tile 16x64),
// ldmatrix fragment loads, cp.async double buffer, fused epilogues.
//   mode 0: projections + LayerNorm/l2   grid (1, 32, 4)
//   mode 1: head + softmax/finalize      grid (4, 128, 1)
// ---------------------------------------------------------------------------
__global__ void __launch_bounds__(512, 1) gemm_fused(
    int mode,
    const float* b0, const float* b1, const float* b2, const float* b3,
    const float* G0, const float* G1, const float* G2, const float* G3,
    const float* e0, const float* e1, const float* e2, const float* e3,
    const float* cls, float* out_logits, float* out_r,
    float* out_sim, float* out_contrib)
{
    extern __shared__ char smem[];
    const uint32_t sbase = smem_u32(smem);
    const int tid = threadIdx.x, wid = tid >> 5, lane = tid & 31;
    float* smf   = (float*)(smem + SM_PARAM);
    float* smred = (float*)(smem + SM_RED);
    float* smst  = (float*)(smem + SM_STAT);

    const int md = (mode == 0) ? blockIdx.z : 0;
    if (mode == 0 && tid < 256) {
        const float* bp = md == 0 ? b0 : md == 1 ? b1 : md == 2 ? b2 : b3;
        const float* gp = md == 0 ? G0 : md == 1 ? G1 : md == 2 ? G2 : G3;
        const float* ep = md == 0 ? e0 : md == 1 ? e1 : md == 2 ? e2 : e3;
        smf[tid] = bp[tid]; smf[256 + tid] = gp[tid]; smf[512 + tid] = ep[tid];
    }
    __syncthreads();

    // operand pointers
    const __nv_bfloat16 *Ah, *Al, *Bh, *Bl;
    int lda, ldb, K;
    const int row0 = blockIdx.y * 64;
    if (mode == 0) {
        const long foff[4] = {0, 2097152, 4194304, 5242880};
        const long woff[4] = {0, 262144, 524288, 655360};
        const int  Km[4]   = {1024, 1024, 512, 256};
        K = Km[md];
        Ah = g_fhi + foff[md] + (long)row0 * K;
        Al = g_flo + foff[md] + (long)row0 * K;
        Bh = g_whi + woff[md];
        Bl = g_wlo + woff[md];
        lda = ldb = K;
    } else {
        K = DD;
        Ah = g_Zhi + (long)row0 * DD;
        Al = g_Zlo + (long)row0 * DD;
        Bh = g_Bhi + (long)blockIdx.x * 256 * DD;
        Bl = g_Blo + (long)blockIdx.x * 256 * DD;
        lda = ldb = DD;
    }
    const int nkt = K >> 5;

    const int wm = wid >> 2, wn = wid & 3;    // 4x4 warp grid, warp tile 16x64
    const int g = lane >> 2, t4 = lane & 3;

    // ldmatrix per-lane byte offsets within a stage
    const uint32_t aoff = ((wm * 16 + (lane & 15)) * 40 + ((lane >> 4) << 3)) * 2;
    const uint32_t boff = ((wn * 64 + (lane & 7) + ((lane >> 4) << 3)) * 40
                           + (((lane >> 3) & 1) << 3)) * 2;

    float acc[8][4];
#pragma unroll
    for (int jn = 0; jn < 8; jn++)
#pragma unroll
        for (int q = 0; q < 4; q++) acc[jn][q] = 0.f;

    // ---------------- cp.async double-buffered mainloop ----------------
    load_stage_async(sbase + SM_T, Ah, Al, Bh, Bl, lda, ldb, 0, tid);
    for (int kt = 0; kt < nkt; kt++) {
        const bool hasNext = (kt + 1 < nkt);
        if (hasNext)
            load_stage_async(sbase + SM_T + ((kt + 1) & 1) * STAGE_B,
                             Ah, Al, Bh, Bl, lda, ldb, (kt + 1) << 5, tid);
        if (hasNext) CP_WAIT1(); else CP_WAIT0();
        __syncthreads();

        const uint32_t sst = sbase + SM_T + (kt & 1) * STAGE_B;
#pragma unroll
        for (int ks = 0; ks < 64; ks += 32) {   // bytes: one k16 step = 32 B
            uint32_t ah[4], al[4], bh[4][4], bl[4][4];
            LDM4(ah, sst + aoff + ks);
            LDM4(al, sst + 5120 + aoff + ks);
#pragma unroll
            for (int jj = 0; jj < 4; jj++) {
                LDM4(bh[jj], sst + 10240 + boff + jj * 1280 + ks);
                LDM4(bl[jj], sst + 30720 + boff + jj * 1280 + ks);
            }
#pragma unroll
            for (int jj = 0; jj < 4; jj++) {
                MMA_BF16(acc[2 * jj],     ah, &bh[jj][0]);
                MMA_BF16(acc[2 * jj],     ah, &bl[jj][0]);
                MMA_BF16(acc[2 * jj],     al, &bh[jj][0]);
                MMA_BF16(acc[2 * jj + 1], ah, &bh[jj][2]);
                MMA_BF16(acc[2 * jj + 1], ah, &bl[jj][2]);
                MMA_BF16(acc[2 * jj + 1], al, &bh[jj][2]);
            }
        }
        __syncthreads();
    }

    // ---------------- fused register epilogue ----------------
    // thread owns rows: wm*16 + g + 8h (h in {0,1})
    //          cols:    wn*64 + jn*8 + 2*t4 + e (jn 0..7, e in {0,1})
    if (mode == 0) {
        // pass 1: y = acc + bias; per-row partial sums
        float sums[2] = {0.f, 0.f}, ssqs[2] = {0.f, 0.f};
#pragma unroll
        for (int jn = 0; jn < 8; jn++)
#pragma unroll
            for (int h = 0; h < 2; h++)
#pragma unroll
                for (int e = 0; e < 2; e++) {
                    const int col = wn * 64 + jn * 8 + 2 * t4 + e;
                    const float y = acc[jn][h * 2 + e] + smf[col];
                    acc[jn][h * 2 + e] = y;
                    sums[h] += y; ssqs[h] += y * y;
                }
#pragma unroll
        for (int h = 0; h < 2; h++) {
            sums[h] += __shfl_xor_sync(0xffffffffu, sums[h], 1);
            sums[h] += __shfl_xor_sync(0xffffffffu, sums[h], 2);
            ssqs[h] += __shfl_xor_sync(0xffffffffu, ssqs[h], 1);
            ssqs[h] += __shfl_xor_sync(0xffffffffu, ssqs[h], 2);
        }
        if (t4 == 0) {
#pragma unroll
            for (int h = 0; h < 2; h++) {
                const int row = wm * 16 + g + 8 * h;
                smred[wn * 128 + row * 2]     = sums[h];
                smred[wn * 128 + row * 2 + 1] = ssqs[h];
            }
        }
        __syncthreads();
        if (tid < 64) {
            float s = 0.f, q = 0.f;
#pragma unroll
            for (int w = 0; w < 4; w++) {
                s += smred[w * 128 + tid * 2];
                q += smred[w * 128 + tid * 2 + 1];
            }
            const float mu = s * (1.f / 256.f);
            const float var = q * (1.f / 256.f) - mu * mu;
            smst[tid * 2]     = mu;
            smst[tid * 2 + 1] = rsqrtf(var + 1e-5f);
        }
        __syncthreads();

        // pass 2: z = LN(y)*gamma+beta -> bf16 hi/lo; accumulate ||z||^2
        float z2[2] = {0.f, 0.f};
#pragma unroll
        for (int h = 0; h < 2; h++) {
            const int row = wm * 16 + g + 8 * h;
            const float mu = smst[row * 2], rstd = smst[row * 2 + 1];
            const long zrow = ((long)(row0 + row) * 4 + md) * 256;
#pragma unroll
            for (int jn = 0; jn < 8; jn++) {
                const int c0 = wn * 64 + jn * 8 + 2 * t4;
                const float z0 = (acc[jn][h * 2]     - mu) * rstd * smf[256 + c0]     + smf[512 + c0];
                const float z1 = (acc[jn][h * 2 + 1] - mu) * rstd * smf[256 + c0 + 1] + smf[512 + c0 + 1];
                z2[h] += z0 * z0 + z1 * z1;
                __nv_bfloat16 h0, l0, h1, l1;
                split2(z0, h0, l0); split2(z1, h1, l1);
                *(uint32_t*)(g_Zhi + zrow + c0) = pack2(h0, h1);
                *(uint32_t*)(g_Zlo + zrow + c0) = pack2(l0, l1);
            }
        }
#pragma unroll
        for (int h = 0; h < 2; h++) {
            z2[h] += __shfl_xor_sync(0xffffffffu, z2[h], 1);
            z2[h] += __shfl_xor_sync(0xffffffffu, z2[h], 2);
        }
        __syncthreads();   // smred/smst reads above complete before reuse
        if (t4 == 0) {
#pragma unroll
            for (int h = 0; h < 2; h++) {
                const int row = wm * 16 + g + 8 * h;
                smred[wn * 128 + row * 2] = z2[h];
            }
        }
        __syncthreads();
        if (tid < 64) {
            float n2 = 0.f;
#pragma unroll
            for (int w = 0; w < 4; w++) n2 += smred[w * 128 + tid * 2];
            g_rnorm[((long)(row0 + tid) * 4 + md)] = 1.f / (sqrtf(n2) + 1e-6f);
        }
    } else {
        // head: col pair (even,odd) = (Z.Un_cg, Z.O_cg); softmax over m via
        // shfl xor 4,8 (modality m = g & 3 lives in lane bits 2..3).
#pragma unroll
        for (int h = 0; h < 2; h++) {
            const long grow = row0 + wm * 16 + g + 8 * h;   // = b*4 + m
            const float rs = g_rnorm[grow] * INVTAU;
#pragma unroll
            for (int jn = 0; jn < 8; jn++) {
                const float s = acc[jn][h * 2] * rs;
                const float o = acc[jn][h * 2 + 1];
                float mx = s;
                mx = fmaxf(mx, __shfl_xor_sync(0xffffffffu, mx, 4));
                mx = fmaxf(mx, __shfl_xor_sync(0xffffffffu, mx, 8));
                const float e = __expf(s - mx);
                float tt = e + __shfl_xor_sync(0xffffffffu, e, 4);
                tt += __shfl_xor_sync(0xffffffffu, tt, 8);
                const float rr = e / tt;
                const float ct = o * rr;
                float lg = ct + __shfl_xor_sync(0xffffffffu, ct, 4);
                lg += __shfl_xor_sync(0xffffffffu, lg, 8);
                const int cg = blockIdx.x * 128 + wn * 32 + jn * 4 + t4;
                const long obase = grow * 512 + cg;
                out_sim[obase]     = s;
                out_r[obase]       = rr;
                out_contrib[obase] = ct;
                if ((grow & 3) == 0)
                    out_logits[(grow >> 2) * 512 + cg] = lg + __ldg(cls + cg);
            }
        }
    }
}

// ---------------------------------------------------------------------------
// fp32 -> bf16 hi/lo conversion for f_* and W_*
// ---------------------------------------------------------------------------
__global__ void __launch_bounds__(256) cvt_fw(
    const float* f0, const float* f1, const float* f2, const float* f3,
    const float* w0, const float* w1, const float* w2, const float* w3)
{
    const int cum[8] = {2048, 4096, 5120, 5632, 5888, 6144, 6272, 6336};
    int blk = blockIdx.x, seg = 0;
    while (blk >= cum[seg]) seg++;
    int lb = blk - (seg ? cum[seg - 1] : 0);
    const float* src;
    __nv_bfloat16 *hi, *lo;
    switch (seg) {
        case 0: src = f0; hi = g_fhi;           lo = g_flo;           break;
        case 1: src = f1; hi = g_fhi + 2097152; lo = g_flo + 2097152; break;
        case 2: src = f2; hi = g_fhi + 4194304; lo = g_flo + 4194304; break;
        case 3: src = f3; hi = g_fhi + 5242880; lo = g_flo + 5242880; break;
        case 4: src = w0; hi = g_whi;           lo = g_wlo;           break;
        case 5: src = w1; hi = g_whi + 262144;  lo = g_wlo + 262144;  break;
        case 6: src = w2; hi = g_whi + 524288;  lo = g_wlo + 524288;  break;
        default:src = w3; hi = g_whi + 655360;  lo = g_wlo + 655360;  break;
    }
    long base = (long)lb * 1024 + threadIdx.x * 4;
    float4 v = *(const float4*)(src + base);
    __nv_bfloat16 h0, h1, h2, h3, l0, l1, l2, l3;
    split2(v.x, h0, l0); split2(v.y, h1, l1);
    split2(v.z, h2, l2); split2(v.w, h3, l3);
    *(__nv_bfloat162*)(hi + base)     = __halves2bfloat162(h0, h1);
    *(__nv_bfloat162*)(hi + base + 2) = __halves2bfloat162(h2, h3);
    *(__nv_bfloat162*)(lo + base)     = __halves2bfloat162(l0, l1);
    *(__nv_bfloat162*)(lo + base + 2) = __halves2bfloat162(l2, l3);
}

// ---------------------------------------------------------------------------
// Bcat rows interleaved: row 2c = l2norm(U)_c, row 2c+1 = O_c  -> bf16 hi/lo
// ---------------------------------------------------------------------------
__global__ void __launch_bounds__(256) normcat_kernel(const float* __restrict__ U,
                                                      const float* __restrict__ O)
{
    const int rr = blockIdx.x, t = threadIdx.x;
    const int c = rr >> 1, kind = rr & 1;
    __shared__ float ws[8];
    float v;
    if (kind == 0) {
        float u = U[(long)c * DD + t];
        float q = u * u;
#pragma unroll
        for (int o = 16; o > 0; o >>= 1) q += __shfl_xor_sync(0xffffffffu, q, o);
        if ((t & 31) == 0) ws[t >> 5] = q;
        __syncthreads();
        float n2 = 0.f;
#pragma unroll
        for (int i = 0; i < 8; i++) n2 += ws[i];
        v = u / (sqrtf(n2) + 1e-6f);
    } else {
        v = O[(long)c * DD + t];
    }
    __nv_bfloat16 h, l; split2(v, h, l);
    g_Bhi[(long)rr * DD + t] = h;
    g_Blo[(long)rr * DD + t] = l;
}

// ---------------------------------------------------------------------------
extern "C" void kernel_launch(void* const* d_in, const int* in_sizes, int n_in,
                              void* d_out, int out_size)
{
    const float *f[4], *W[4], *bi[4], *ga[4], *be[4];
    if (in_sizes[1] == 256 * 1024) {   // dict order: (f,W,b,g,be) per modality
        for (int m = 0; m < 4; m++) {
            f[m]  = (const float*)d_in[m * 5 + 0];
            W[m]  = (const float*)d_in[m * 5 + 1];
            bi[m] = (const float*)d_in[m * 5 + 2];
            ga[m] = (const float*)d_in[m * 5 + 3];
            be[m] = (const float*)d_in[m * 5 + 4];
        }
    } else {                            // signature order
        for (int m = 0; m < 4; m++) f[m] = (const float*)d_in[m];
        for (int m = 0; m < 4; m++) {
            W[m]  = (const float*)d_in[4 + m * 4 + 0];
            bi[m] = (const float*)d_in[4 + m * 4 + 1];
            ga[m] = (const float*)d_in[4 + m * 4 + 2];
            be[m] = (const float*)d_in[4 + m * 4 + 3];
        }
    }
    const float* U   = (const float*)d_in[20];
    const float* O   = (const float*)d_in[21];
    const float* cls = (const float*)d_in[22];

    float* out         = (float*)d_out;
    float* out_logits  = out;
    float* out_r       = out + (long)BB * CC;
    float* out_sim     = out_r + (long)NROW * CC;
    float* out_contrib = out_sim + (long)NROW * CC;

    cudaFuncSetAttribute(gemm_fused, cudaFuncAttributeMaxDynamicSharedMemorySize, SMEM_TOTAL);

    cvt_fw<<<6336, 256>>>(f[0], f[1], f[2], f[3], W[0], W[1], W[2], W[3]);
    normcat_kernel<<<1024, 256>>>(U, O);

    // projections + fused LayerNorm/l2 (Z emitted as bf16 hi/lo, rnorm filled)
    gemm_fused<<<dim3(1, 32, 4), 512, SMEM_TOTAL>>>(
        0, bi[0], bi[1], bi[2], bi[3], ga[0], ga[1], ga[2], ga[3],
        be[0], be[1], be[2], be[3], nullptr, nullptr, nullptr, nullptr, nullptr);

    // head GEMM + fused softmax/finalize (writes all four outputs)
    gemm_fused<<<dim3(4, 128, 1), 512, SMEM_TOTAL>>>(
        1, nullptr, nullptr, nullptr, nullptr, nullptr, nullptr, nullptr, nullptr,
        nullptr, nullptr, nullptr, nullptr, cls, out_logits, out_r, out_sim, out_contrib);
}

// round 10
// speedup vs baseline: 1.6639x; 1.1533x over previous
#include <cuda_runtime.h>
#include <cuda_bf16.h>
#include <math.h>
#include <stdint.h>

#define BB 2048
#define DD 256
#define CC 512
#define NROW 8192
#define INVTAU (1.0f/0.07f)
#define FTOT 5767168   // 2048*(1024+1024+512+256)
#define WTOT 720896    // 256*(1024+1024+512+256)

// ---------------- scratch (no allocations allowed) ----------------
__device__ __nv_bfloat16 g_fhi[FTOT], g_flo[FTOT];
__device__ __nv_bfloat16 g_whi[WTOT], g_wlo[WTOT];
__device__ __nv_bfloat16 g_Zhi[NROW * DD], g_Zlo[NROW * DD];
__device__ __nv_bfloat16 g_Bhi[1024 * DD], g_Blo[1024 * DD]; // interleaved rows: 2c=Un_c, 2c+1=O_c
__device__ float         g_rnorm[NROW];

#define MMA_BF16(d, a, b) asm volatile( \
    "mma.sync.aligned.m16n8k16.row.col.f32.bf16.bf16.f32 " \
    "{%0,%1,%2,%3}, {%4,%5,%6,%7}, {%8,%9}, {%0,%1,%2,%3};\n" \
    : "+f"((d)[0]), "+f"((d)[1]), "+f"((d)[2]), "+f"((d)[3]) \
    : "r"((a)[0]), "r"((a)[1]), "r"((a)[2]), "r"((a)[3]), "r"((b)[0]), "r"((b)[1]))

#define LDM4(r, addr) asm volatile( \
    "ldmatrix.sync.aligned.m8n8.x4.shared.b16 {%0,%1,%2,%3}, [%4];" \
    : "=r"((r)[0]), "=r"((r)[1]), "=r"((r)[2]), "=r"((r)[3]) : "r"(addr))

#define CP16(dst, src) asm volatile("cp.async.cg.shared.global [%0], [%1], 16;" :: "r"(dst), "l"(src))
#define CP_COMMIT()    asm volatile("cp.async.commit_group;" ::: "memory")
#define CP_WAIT0()     asm volatile("cp.async.wait_group 0;" ::: "memory")
#define CP_WAIT1()     asm volatile("cp.async.wait_group 1;" ::: "memory")

__device__ __forceinline__ uint32_t smem_u32(const void* p) {
    uint32_t a;
    asm("{ .reg .u64 t; cvta.to.shared.u64 t, %1; cvt.u32.u64 %0, t; }" : "=r"(a) : "l"(p));
    return a;
}
__device__ __forceinline__ void split2(float x, __nv_bfloat16& h, __nv_bfloat16& l) {
    h = __float2bfloat16_rn(x);
    l = __float2bfloat16_rn(x - __bfloat162float(h));
}
__device__ __forceinline__ uint32_t pack2(__nv_bfloat16 a, __nv_bfloat16 b) {
    __nv_bfloat162 t = __halves2bfloat162(a, b);
    return *(uint32_t*)&t;
}

// smem layout (dynamic):
//  [0]     params: bias|gamma|beta (768 f)          3072 B
//  [3072]  smred: 4 warp-cols x 64 rows x 2         2048 B
//  [5120]  stats: 64 rows x 2 (mu,rstd)              512 B
//  [5632]  tiles: 2 stages x 51200 B              102400 B
//          per stage (byte offsets, 80 B/row stride, 64 B data):
//          Ahi 0 | Alo 5120 | Bhi 10240 | Blo 30720
#define SM_PARAM 0
#define SM_RED   3072
#define SM_STAT  5120
#define SM_T     5632
#define STAGE_B  51200
#define SMEM_TOTAL (SM_T + 2 * STAGE_B)   // 108032  -> 2 CTAs/SM

// issue cp.async for one K32 stage: A 64 rows, B 256 rows, hi+lo (256 threads)
__device__ __forceinline__ void load_stage_async(
    uint32_t tile_sm, const __nv_bfloat16* Ah, const __nv_bfloat16* Al,
    const __nv_bfloat16* Bh, const __nv_bfloat16* Bl,
    int lda, int ldb, int k0, int tid)
{
#pragma unroll
    for (int i = 0; i < 2; i++) {   // A: 2 arrays x 256 uint4
        const int n = tid + (i << 8);
        const int a = n >> 8, idx = n & 255;
        const int row = idx >> 2, ch = idx & 3;
        const __nv_bfloat16* src = a ? Al : Ah;
        const char* gsrc = (const char*)(src + (long)row * lda + k0 + (ch << 3));
        CP16(tile_sm + a * 5120 + row * 80 + (ch << 4), gsrc);
    }
#pragma unroll
    for (int i = 0; i < 8; i++) {   // B: 2 arrays x 1024 uint4
        const int m = tid + (i << 8);
        const int a = m >> 10, idx = m & 1023;
        const int row = idx >> 2, ch = idx & 3;
        const __nv_bfloat16* src = a ? Bl : Bh;
        const char* gsrc = (const char*)(src + (long)row * ldb + k0 + (ch << 3));
        CP16(tile_sm + 10240 + a * 20480 + row * 80 + (ch << 4), gsrc);
    }
    CP_COMMIT();
}

// ---------------------------------------------------------------------------
// CTA tile 64 rows x 256 cols, 256 threads, warp grid 2x4 (warp tile 32x64),
// ldmatrix loads, cp.async double buffer, fused epilogues, 2 CTAs/SM.
//   mode 0: projections + LayerNorm/l2   grid (1, 32, 4)
//   mode 1: head + softmax/finalize      grid (4, 128, 1)
// ---------------------------------------------------------------------------
__global__ void __launch_bounds__(256, 2) gemm_fused(
    int mode,
    const float* b0, const float* b1, const float* b2, const float* b3,
    const float* G0, const float* G1, const float* G2, const float* G3,
    const float* e0, const float* e1, const float* e2, const float* e3,
    const float* cls, float* out_logits, float* out_r,
    float* out_sim, float* out_contrib)
{
    extern __shared__ char smem[];
    const uint32_t sbase = smem_u32(smem);
    const int tid = threadIdx.x, wid = tid >> 5, lane = tid & 31;
    float* smf   = (float*)(smem + SM_PARAM);
    float* smred = (float*)(smem + SM_RED);
    float* smst  = (float*)(smem + SM_STAT);

    const int md = (mode == 0) ? blockIdx.z : 0;
    if (mode == 0) {
        const float* bp = md == 0 ? b0 : md == 1 ? b1 : md == 2 ? b2 : b3;
        const float* gp = md == 0 ? G0 : md == 1 ? G1 : md == 2 ? G2 : G3;
        const float* ep = md == 0 ? e0 : md == 1 ? e1 : md == 2 ? e2 : e3;
        smf[tid] = bp[tid]; smf[256 + tid] = gp[tid]; smf[512 + tid] = ep[tid];
    }
    __syncthreads();

    // operand pointers
    const __nv_bfloat16 *Ah, *Al, *Bh, *Bl;
    int lda, ldb, K;
    const int row0 = blockIdx.y * 64;
    if (mode == 0) {
        const long foff[4] = {0, 2097152, 4194304, 5242880};
        const long woff[4] = {0, 262144, 524288, 655360};
        const int  Km[4]   = {1024, 1024, 512, 256};
        K = Km[md];
        Ah = g_fhi + foff[md] + (long)row0 * K;
        Al = g_flo + foff[md] + (long)row0 * K;
        Bh = g_whi + woff[md];
        Bl = g_wlo + woff[md];
        lda = ldb = K;
    } else {
        K = DD;
        Ah = g_Zhi + (long)row0 * DD;
        Al = g_Zlo + (long)row0 * DD;
        Bh = g_Bhi + (long)blockIdx.x * 256 * DD;
        Bl = g_Blo + (long)blockIdx.x * 256 * DD;
        lda = ldb = DD;
    }
    const int nkt = K >> 5;

    const int wm = wid >> 2, wn = wid & 3;    // 2x4 warp grid, warp tile 32x64
    const int g = lane >> 2, t4 = lane & 3;

    // ldmatrix per-lane byte offsets within a stage (proven in round 8)
    uint32_t aoff[2];
#pragma unroll
    for (int im = 0; im < 2; im++)
        aoff[im] = ((wm * 32 + im * 16 + (lane & 15)) * 40 + ((lane >> 4) << 3)) * 2;
    const uint32_t boff = ((wn * 64 + (lane & 7) + ((lane >> 4) << 3)) * 40
                           + (((lane >> 3) & 1) << 3)) * 2;

    float acc[2][8][4];
#pragma unroll
    for (int im = 0; im < 2; im++)
#pragma unroll
        for (int jn = 0; jn < 8; jn++)
#pragma unroll
            for (int q = 0; q < 4; q++) acc[im][jn][q] = 0.f;

    // ---------------- cp.async double-buffered mainloop ----------------
    load_stage_async(sbase + SM_T, Ah, Al, Bh, Bl, lda, ldb, 0, tid);
    for (int kt = 0; kt < nkt; kt++) {
        const bool hasNext = (kt + 1 < nkt);
        if (hasNext)
            load_stage_async(sbase + SM_T + ((kt + 1) & 1) * STAGE_B,
                             Ah, Al, Bh, Bl, lda, ldb, (kt + 1) << 5, tid);
        if (hasNext) CP_WAIT1(); else CP_WAIT0();
        __syncthreads();

        const uint32_t sst = sbase + SM_T + (kt & 1) * STAGE_B;
#pragma unroll
        for (int ks = 0; ks < 64; ks += 32) {   // one k16 step = 32 B
            uint32_t ah[2][4], al[2][4];
#pragma unroll
            for (int im = 0; im < 2; im++) {
                LDM4(ah[im], sst + aoff[im] + ks);
                LDM4(al[im], sst + 5120 + aoff[im] + ks);
            }
#pragma unroll
            for (int jj = 0; jj < 4; jj++) {
                uint32_t bh[4], bl[4];
                LDM4(bh, sst + 10240 + boff + jj * 1280 + ks);
                LDM4(bl, sst + 30720 + boff + jj * 1280 + ks);
#pragma unroll
                for (int im = 0; im < 2; im++) {
                    MMA_BF16(acc[im][2 * jj],     ah[im], &bh[0]);
                    MMA_BF16(acc[im][2 * jj],     ah[im], &bl[0]);
                    MMA_BF16(acc[im][2 * jj],     al[im], &bh[0]);
                    MMA_BF16(acc[im][2 * jj + 1], ah[im], &bh[2]);
                    MMA_BF16(acc[im][2 * jj + 1], ah[im], &bl[2]);
                    MMA_BF16(acc[im][2 * jj + 1], al[im], &bh[2]);
                }
            }
        }
        __syncthreads();
    }

    // ---------------- fused register epilogue ----------------
    // thread owns rows: wm*32 + im*16 + g + 8h (im,h in {0,1})
    //          cols:    wn*64 + jn*8 + 2*t4 + e (jn 0..7, e in {0,1})
    if (mode == 0) {
        // pass 1: y = acc + bias; per-row partial sums
        float sums[2][2] = {{0, 0}, {0, 0}}, ssqs[2][2] = {{0, 0}, {0, 0}};
#pragma unroll
        for (int im = 0; im < 2; im++)
#pragma unroll
            for (int jn = 0; jn < 8; jn++)
#pragma unroll
                for (int h = 0; h < 2; h++)
#pragma unroll
                    for (int e = 0; e < 2; e++) {
                        const int col = wn * 64 + jn * 8 + 2 * t4 + e;
                        const float y = acc[im][jn][h * 2 + e] + smf[col];
                        acc[im][jn][h * 2 + e] = y;
                        sums[im][h] += y; ssqs[im][h] += y * y;
                    }
#pragma unroll
        for (int im = 0; im < 2; im++)
#pragma unroll
            for (int h = 0; h < 2; h++) {
                sums[im][h] += __shfl_xor_sync(0xffffffffu, sums[im][h], 1);
                sums[im][h] += __shfl_xor_sync(0xffffffffu, sums[im][h], 2);
                ssqs[im][h] += __shfl_xor_sync(0xffffffffu, ssqs[im][h], 1);
                ssqs[im][h] += __shfl_xor_sync(0xffffffffu, ssqs[im][h], 2);
            }
        if (t4 == 0) {
#pragma unroll
            for (int im = 0; im < 2; im++)
#pragma unroll
                for (int h = 0; h < 2; h++) {
                    const int row = wm * 32 + im * 16 + g + 8 * h;
                    smred[wn * 128 + row * 2]     = sums[im][h];
                    smred[wn * 128 + row * 2 + 1] = ssqs[im][h];
                }
        }
        __syncthreads();
        if (tid < 64) {
            float s = 0.f, q = 0.f;
#pragma unroll
            for (int w = 0; w < 4; w++) {
                s += smred[w * 128 + tid * 2];
                q += smred[w * 128 + tid * 2 + 1];
            }
            const float mu = s * (1.f / 256.f);
            const float var = q * (1.f / 256.f) - mu * mu;
            smst[tid * 2]     = mu;
            smst[tid * 2 + 1] = rsqrtf(var + 1e-5f);
        }
        __syncthreads();

        // pass 2: z = LN(y)*gamma+beta -> bf16 hi/lo; accumulate ||z||^2
        float z2[2][2] = {{0, 0}, {0, 0}};
#pragma unroll
        for (int im = 0; im < 2; im++)
#pragma unroll
            for (int h = 0; h < 2; h++) {
                const int row = wm * 32 + im * 16 + g + 8 * h;
                const float mu = smst[row * 2], rstd = smst[row * 2 + 1];
                const long zrow = ((long)(row0 + row) * 4 + md) * 256;
#pragma unroll
                for (int jn = 0; jn < 8; jn++) {
                    const int c0 = wn * 64 + jn * 8 + 2 * t4;
                    const float z0 = (acc[im][jn][h * 2]     - mu) * rstd * smf[256 + c0]     + smf[512 + c0];
                    const float z1 = (acc[im][jn][h * 2 + 1] - mu) * rstd * smf[256 + c0 + 1] + smf[512 + c0 + 1];
                    z2[im][h] += z0 * z0 + z1 * z1;
                    __nv_bfloat16 h0, l0, h1, l1;
                    split2(z0, h0, l0); split2(z1, h1, l1);
                    *(uint32_t*)(g_Zhi + zrow + c0) = pack2(h0, h1);
                    *(uint32_t*)(g_Zlo + zrow + c0) = pack2(l0, l1);
                }
            }
#pragma unroll
        for (int im = 0; im < 2; im++)
#pragma unroll
            for (int h = 0; h < 2; h++) {
                z2[im][h] += __shfl_xor_sync(0xffffffffu, z2[im][h], 1);
                z2[im][h] += __shfl_xor_sync(0xffffffffu, z2[im][h], 2);
            }
        __syncthreads();   // smred/smst reads above complete before reuse
        if (t4 == 0) {
#pragma unroll
            for (int im = 0; im < 2; im++)
#pragma unroll
                for (int h = 0; h < 2; h++) {
                    const int row = wm * 32 + im * 16 + g + 8 * h;
                    smred[wn * 128 + row * 2] = z2[im][h];
                }
        }
        __syncthreads();
        if (tid < 64) {
            float n2 = 0.f;
#pragma unroll
            for (int w = 0; w < 4; w++) n2 += smred[w * 128 + tid * 2];
            g_rnorm[((long)(row0 + tid) * 4 + md)] = 1.f / (sqrtf(n2) + 1e-6f);
        }
    } else {
        // head: col pair (even,odd) = (Z.Un_cg, Z.O_cg); softmax over m via
        // shfl xor 4,8 (modality m = grow&3 = g&3 lives in lane bits 2..3).
#pragma unroll
        for (int im = 0; im < 2; im++)
#pragma unroll
            for (int h = 0; h < 2; h++) {
                const long grow = row0 + wm * 32 + im * 16 + g + 8 * h;   // = b*4 + m
                const float rs = g_rnorm[grow] * INVTAU;
#pragma unroll
                for (int jn = 0; jn < 8; jn++) {
                    const float s = acc[im][jn][h * 2] * rs;
                    const float o = acc[im][jn][h * 2 + 1];
                    float mx = s;
                    mx = fmaxf(mx, __shfl_xor_sync(0xffffffffu, mx, 4));
                    mx = fmaxf(mx, __shfl_xor_sync(0xffffffffu, mx, 8));
                    const float e = __expf(s - mx);
                    float tt = e + __shfl_xor_sync(0xffffffffu, e, 4);
                    tt += __shfl_xor_sync(0xffffffffu, tt, 8);
                    const float rr = e / tt;
                    const float ct = o * rr;
                    float lg = ct + __shfl_xor_sync(0xffffffffu, ct, 4);
                    lg += __shfl_xor_sync(0xffffffffu, lg, 8);
                    const int cg = blockIdx.x * 128 + wn * 32 + jn * 4 + t4;
                    const long obase = grow * 512 + cg;
                    out_sim[obase]     = s;
                    out_r[obase]       = rr;
                    out_contrib[obase] = ct;
                    if ((grow & 3) == 0)
                        out_logits[(grow >> 2) * 512 + cg] = lg + __ldg(cls + cg);
                }
            }
    }
}

// ---------------------------------------------------------------------------
// fp32 -> bf16 hi/lo conversion for f_* and W_*
// ---------------------------------------------------------------------------
__global__ void __launch_bounds__(256) cvt_fw(
    const float* f0, const float* f1, const float* f2, const float* f3,
    const float* w0, const float* w1, const float* w2, const float* w3)
{
    const int cum[8] = {2048, 4096, 5120, 5632, 5888, 6144, 6272, 6336};
    int blk = blockIdx.x, seg = 0;
    while (blk >= cum[seg]) seg++;
    int lb = blk - (seg ? cum[seg - 1] : 0);
    const float* src;
    __nv_bfloat16 *hi, *lo;
    switch (seg) {
        case 0: src = f0; hi = g_fhi;           lo = g_flo;           break;
        case 1: src = f1; hi = g_fhi + 2097152; lo = g_flo + 2097152; break;
        case 2: src = f2; hi = g_fhi + 4194304; lo = g_flo + 4194304; break;
        case 3: src = f3; hi = g_fhi + 5242880; lo = g_flo + 5242880; break;
        case 4: src = w0; hi = g_whi;           lo = g_wlo;           break;
        case 5: src = w1; hi = g_whi + 262144;  lo = g_wlo + 262144;  break;
        case 6: src = w2; hi = g_whi + 524288;  lo = g_wlo + 524288;  break;
        default:src = w3; hi = g_whi + 655360;  lo = g_wlo + 655360;  break;
    }
    long base = (long)lb * 1024 + threadIdx.x * 4;
    float4 v = *(const float4*)(src + base);
    __nv_bfloat16 h0, h1, h2, h3, l0, l1, l2, l3;
    split2(v.x, h0, l0); split2(v.y, h1, l1);
    split2(v.z, h2, l2); split2(v.w, h3, l3);
    *(__nv_bfloat162*)(hi + base)     = __halves2bfloat162(h0, h1);
    *(__nv_bfloat162*)(hi + base + 2) = __halves2bfloat162(h2, h3);
    *(__nv_bfloat162*)(lo + base)     = __halves2bfloat162(l0, l1);
    *(__nv_bfloat162*)(lo + base + 2) = __halves2bfloat162(l2, l3);
}

// ---------------------------------------------------------------------------
// Bcat rows interleaved: row 2c = l2norm(U)_c, row 2c+1 = O_c  -> bf16 hi/lo
// ---------------------------------------------------------------------------
__global__ void __launch_bounds__(256) normcat_kernel(const float* __restrict__ U,
                                                      const float* __restrict__ O)
{
    const int rr = blockIdx.x, t = threadIdx.x;
    const int c = rr >> 1, kind = rr & 1;
    __shared__ float ws[8];
    float v;
    if (kind == 0) {
        float u = U[(long)c * DD + t];
        float q = u * u;
#pragma unroll
        for (int o = 16; o > 0; o >>= 1) q += __shfl_xor_sync(0xffffffffu, q, o);
        if ((t & 31) == 0) ws[t >> 5] = q;
        __syncthreads();
        float n2 = 0.f;
#pragma unroll
        for (int i = 0; i < 8; i++) n2 += ws[i];
        v = u / (sqrtf(n2) + 1e-6f);
    } else {
        v = O[(long)c * DD + t];
    }
    __nv_bfloat16 h, l; split2(v, h, l);
    g_Bhi[(long)rr * DD + t] = h;
    g_Blo[(long)rr * DD + t] = l;
}

// ---------------------------------------------------------------------------
extern "C" void kernel_launch(void* const* d_in, const int* in_sizes, int n_in,
                              void* d_out, int out_size)
{
    const float *f[4], *W[4], *bi[4], *ga[4], *be[4];
    if (in_sizes[1] == 256 * 1024) {   // dict order: (f,W,b,g,be) per modality
        for (int m = 0; m < 4; m++) {
            f[m]  = (const float*)d_in[m * 5 + 0];
            W[m]  = (const float*)d_in[m * 5 + 1];
            bi[m] = (const float*)d_in[m * 5 + 2];
            ga[m] = (const float*)d_in[m * 5 + 3];
            be[m] = (const float*)d_in[m * 5 + 4];
        }
    } else {                            // signature order
        for (int m = 0; m < 4; m++) f[m] = (const float*)d_in[m];
        for (int m = 0; m < 4; m++) {
            W[m]  = (const float*)d_in[4 + m * 4 + 0];
            bi[m] = (const float*)d_in[4 + m * 4 + 1];
            ga[m] = (const float*)d_in[4 + m * 4 + 2];
            be[m] = (const float*)d_in[4 + m * 4 + 3];
        }
    }
    const float* U   = (const float*)d_in[20];
    const float* O   = (const float*)d_in[21];
    const float* cls = (const float*)d_in[22];

    float* out         = (float*)d_out;
    float* out_logits  = out;
    float* out_r       = out + (long)BB * CC;
    float* out_sim     = out_r + (long)NROW * CC;
    float* out_contrib = out_sim + (long)NROW * CC;

    cudaFuncSetAttribute(gemm_fused, cudaFuncAttributeMaxDynamicSharedMemorySize, SMEM_TOTAL);

    cvt_fw<<<6336, 256>>>(f[0], f[1], f[2], f[3], W[0], W[1], W[2], W[3]);
    normcat_kernel<<<1024, 256>>>(U, O);

    // projections + fused LayerNorm/l2 (Z emitted as bf16 hi/lo, rnorm filled)
    gemm_fused<<<dim3(1, 32, 4), 256, SMEM_TOTAL>>>(
        0, bi[0], bi[1], bi[2], bi[3], ga[0], ga[1], ga[2], ga[3],
        be[0], be[1], be[2], be[3], nullptr, nullptr, nullptr, nullptr, nullptr);

    // head GEMM + fused softmax/finalize (writes all four outputs)
    gemm_fused<<<dim3(4, 128, 1), 256, SMEM_TOTAL>>>(
        1, nullptr, nullptr, nullptr, nullptr, nullptr, nullptr, nullptr, nullptr,
        nullptr, nullptr, nullptr, nullptr, cls, out_logits, out_r, out_sim, out_contrib);
}

// round 12
// speedup vs baseline: 1.7426x; 1.0473x over previous
#include <cuda_runtime.h>
#include <cuda_bf16.h>
#include <math.h>
#include <stdint.h>

#define BB 2048
#define DD 256
#define CC 512
#define NROW 8192
#define INVTAU (1.0f/0.07f)
#define FTOT 5767168   // 2048*(1024+1024+512+256)
#define WTOT 720896    // 256*(1024+1024+512+256)

// ---------------- scratch (no allocations allowed) ----------------
__device__ __nv_bfloat16 g_fhi[FTOT], g_flo[FTOT];
__device__ __nv_bfloat16 g_whi[WTOT], g_wlo[WTOT];
__device__ __nv_bfloat16 g_Zhi[NROW * DD], g_Zlo[NROW * DD];
__device__ __nv_bfloat16 g_Bhi[1024 * DD], g_Blo[1024 * DD]; // interleaved rows: 2c=Un_c, 2c+1=O_c
__device__ float         g_rnorm[NROW];

#define MMA_BF16(d, a, b) asm volatile( \
    "mma.sync.aligned.m16n8k16.row.col.f32.bf16.bf16.f32 " \
    "{%0,%1,%2,%3}, {%4,%5,%6,%7}, {%8,%9}, {%0,%1,%2,%3};\n" \
    : "+f"((d)[0]), "+f"((d)[1]), "+f"((d)[2]), "+f"((d)[3]) \
    : "r"((a)[0]), "r"((a)[1]), "r"((a)[2]), "r"((a)[3]), "r"((b)[0]), "r"((b)[1]))

#define LDM4(r, addr) asm volatile( \
    "ldmatrix.sync.aligned.m8n8.x4.shared.b16 {%0,%1,%2,%3}, [%4];" \
    : "=r"((r)[0]), "=r"((r)[1]), "=r"((r)[2]), "=r"((r)[3]) : "r"(addr))

#define CP16(dst, src) asm volatile("cp.async.cg.shared.global [%0], [%1], 16;" :: "r"(dst), "l"(src))
#define CP_COMMIT()    asm volatile("cp.async.commit_group;" ::: "memory")
#define CP_WAIT0()     asm volatile("cp.async.wait_group 0;" ::: "memory")
#define CP_WAIT1()     asm volatile("cp.async.wait_group 1;" ::: "memory")

__device__ __forceinline__ uint32_t smem_u32(const void* p) {
    uint32_t a;
    asm("{ .reg .u64 t; cvta.to.shared.u64 t, %1; cvt.u32.u64 %0, t; }" : "=r"(a) : "l"(p));
    return a;
}
__device__ __forceinline__ void split2(float x, __nv_bfloat16& h, __nv_bfloat16& l) {
    h = __float2bfloat16_rn(x);
    l = __float2bfloat16_rn(x - __bfloat162float(h));
}
__device__ __forceinline__ uint32_t pack2(__nv_bfloat16 a, __nv_bfloat16 b) {
    __nv_bfloat162 t = __halves2bfloat162(a, b);
    return *(uint32_t*)&t;
}

// smem layout header (both instantiations):
//  [0]     params: bias|gamma|beta (768 f)          3072 B
//  [3072]  smred: 4 warp-cols x ROWS x 2           <=2048 B
//  [5120]  stats: ROWS x 2 (mu,rstd)                <=512 B
//  [5632]  tiles: 2 stages
//  stage layout (byte offsets, 80 B/row stride, 64 B data per row):
//    Ahi 0 | Alo A_ARR | Bhi 2*A_ARR | Blo 2*A_ARR+20480
#define SM_PARAM 0
#define SM_RED   3072
#define SM_STAT  5120
#define SM_T     5632
#define SMEM1 (SM_T + 2 * (2 * 32 * 80 + 40960))   // 97792  (proj, 32 rows)
#define SMEM2 (SM_T + 2 * (2 * 64 * 80 + 40960))   // 108032 (head, 64 rows)

// issue cp.async for one K32 stage: A ROWS rows, B 256 rows, hi+lo (256 thr)
template<int NIM>
__device__ __forceinline__ void load_stage_async(
    uint32_t tile_sm, const __nv_bfloat16* Ah, const __nv_bfloat16* Al,
    const __nv_bfloat16* Bh, const __nv_bfloat16* Bl,
    int lda, int ldb, int k0, int tid)
{
    constexpr int ROWS  = 32 * NIM;
    constexpr int A_ARR = ROWS * 80;
#pragma unroll
    for (int i = 0; i < NIM; i++) {   // A: 2 arrays x ROWS*4 uint4
        const int n = tid + (i << 8);
        const int a = n / (ROWS * 4), idx = n % (ROWS * 4);
        const int row = idx >> 2, ch = idx & 3;
        const __nv_bfloat16* src = a ? Al : Ah;
        const char* gsrc = (const char*)(src + (long)row * lda + k0 + (ch << 3));
        CP16(tile_sm + a * A_ARR + row * 80 + (ch << 4), gsrc);
    }
#pragma unroll
    for (int i = 0; i < 8; i++) {   // B: 2 arrays x 1024 uint4
        const int m = tid + (i << 8);
        const int a = m >> 10, idx = m & 1023;
        const int row = idx >> 2, ch = idx & 3;
        const __nv_bfloat16* src = a ? Bl : Bh;
        const char* gsrc = (const char*)(src + (long)row * ldb + k0 + (ch << 3));
        CP16(tile_sm + 2 * A_ARR + a * 20480 + row * 80 + (ch << 4), gsrc);
    }
    CP_COMMIT();
}

// ---------------------------------------------------------------------------
// CTA tile (32*NIM) rows x 256 cols, 256 threads, warp grid 2x4
// (warp tile 16*NIM x 64), ldmatrix + cp.async double buffer, fused epilogues.
//   NIM=1, mode 0: projections + LayerNorm/l2   grid (1, 64, 4)  [256 CTAs]
//   NIM=2, mode 1: head + softmax/finalize      grid (4, 128, 1) [512 CTAs]
// ---------------------------------------------------------------------------
template<int NIM>
__global__ void __launch_bounds__(256, 2) gemm_fused(
    int mode,
    const float* b0, const float* b1, const float* b2, const float* b3,
    const float* G0, const float* G1, const float* G2, const float* G3,
    const float* e0, const float* e1, const float* e2, const float* e3,
    const float* cls, float* out_logits, float* out_r,
    float* out_sim, float* out_contrib)
{
    constexpr int ROWS    = 32 * NIM;
    constexpr int A_ARR   = ROWS * 80;
    constexpr int STAGE_B = 2 * A_ARR + 40960;

    extern __shared__ char smem[];
    const uint32_t sbase = smem_u32(smem);
    const int tid = threadIdx.x, wid = tid >> 5, lane = tid & 31;
    float* smf   = (float*)(smem + SM_PARAM);
    float* smred = (float*)(smem + SM_RED);
    float* smst  = (float*)(smem + SM_STAT);

    const int md = (mode == 0) ? blockIdx.z : 0;
    if (mode == 0) {
        const float* bp = md == 0 ? b0 : md == 1 ? b1 : md == 2 ? b2 : b3;
        const float* gp = md == 0 ? G0 : md == 1 ? G1 : md == 2 ? G2 : G3;
        const float* ep = md == 0 ? e0 : md == 1 ? e1 : md == 2 ? e2 : e3;
        smf[tid] = bp[tid]; smf[256 + tid] = gp[tid]; smf[512 + tid] = ep[tid];
    }
    __syncthreads();

    // operand pointers
    const __nv_bfloat16 *Ah, *Al, *Bh, *Bl;
    int lda, ldb, K;
    const int row0 = blockIdx.y * ROWS;
    if (mode == 0) {
        const long foff[4] = {0, 2097152, 4194304, 5242880};
        const long woff[4] = {0, 262144, 524288, 655360};
        const int  Km[4]   = {1024, 1024, 512, 256};
        K = Km[md];
        Ah = g_fhi + foff[md] + (long)row0 * K;
        Al = g_flo + foff[md] + (long)row0 * K;
        Bh = g_whi + woff[md];
        Bl = g_wlo + woff[md];
        lda = ldb = K;
    } else {
        K = DD;
        Ah = g_Zhi + (long)row0 * DD;
        Al = g_Zlo + (long)row0 * DD;
        Bh = g_Bhi + (long)blockIdx.x * 256 * DD;
        Bl = g_Blo + (long)blockIdx.x * 256 * DD;
        lda = ldb = DD;
    }
    const int nkt = K >> 5;

    const int wm = wid >> 2, wn = wid & 3;    // 2x4 warp grid
    const int g = lane >> 2, t4 = lane & 3;

    uint32_t aoff[NIM];
#pragma unroll
    for (int im = 0; im < NIM; im++)
        aoff[im] = ((wm * (16 * NIM) + im * 16 + (lane & 15)) * 40
                    + ((lane >> 4) << 3)) * 2;
    const uint32_t boff = ((wn * 64 + (lane & 7) + ((lane >> 4) << 3)) * 40
                           + (((lane >> 3) & 1) << 3)) * 2;

    float acc[NIM][8][4];
#pragma unroll
    for (int im = 0; im < NIM; im++)
#pragma unroll
        for (int jn = 0; jn < 8; jn++)
#pragma unroll
            for (int q = 0; q < 4; q++) acc[im][jn][q] = 0.f;

    // ---------------- cp.async double-buffered mainloop ----------------
    load_stage_async<NIM>(sbase + SM_T, Ah, Al, Bh, Bl, lda, ldb, 0, tid);
    for (int kt = 0; kt < nkt; kt++) {
        const bool hasNext = (kt + 1 < nkt);
        if (hasNext)
            load_stage_async<NIM>(sbase + SM_T + ((kt + 1) & 1) * STAGE_B,
                                  Ah, Al, Bh, Bl, lda, ldb, (kt + 1) << 5, tid);
        if (hasNext) CP_WAIT1(); else CP_WAIT0();
        __syncthreads();

        const uint32_t sst = sbase + SM_T + (kt & 1) * STAGE_B;
#pragma unroll
        for (int ks = 0; ks < 64; ks += 32) {   // one k16 step = 32 B
            uint32_t ah[NIM][4], al[NIM][4];
#pragma unroll
            for (int im = 0; im < NIM; im++) {
                LDM4(ah[im], sst + aoff[im] + ks);
                LDM4(al[im], sst + A_ARR + aoff[im] + ks);
            }
#pragma unroll
            for (int jj = 0; jj < 4; jj++) {
                uint32_t bh[4], bl[4];
                LDM4(bh, sst + 2 * A_ARR + boff + jj * 1280 + ks);
                LDM4(bl, sst + 2 * A_ARR + 20480 + boff + jj * 1280 + ks);
#pragma unroll
                for (int im = 0; im < NIM; im++) {
                    MMA_BF16(acc[im][2 * jj],     ah[im], &bh[0]);
                    MMA_BF16(acc[im][2 * jj],     ah[im], &bl[0]);
                    MMA_BF16(acc[im][2 * jj],     al[im], &bh[0]);
                    MMA_BF16(acc[im][2 * jj + 1], ah[im], &bh[2]);
                    MMA_BF16(acc[im][2 * jj + 1], ah[im], &bl[2]);
                    MMA_BF16(acc[im][2 * jj + 1], al[im], &bh[2]);
                }
            }
        }
        __syncthreads();
    }

    // ---------------- fused register epilogue ----------------
    // thread rows: wm*(16*NIM) + im*16 + g + 8h   cols: wn*64 + jn*8 + 2*t4 + e
    if (mode == 0) {
        float sums[NIM][2], ssqs[NIM][2];
#pragma unroll
        for (int im = 0; im < NIM; im++)
#pragma unroll
            for (int h = 0; h < 2; h++) { sums[im][h] = 0.f; ssqs[im][h] = 0.f; }
#pragma unroll
        for (int im = 0; im < NIM; im++)
#pragma unroll
            for (int jn = 0; jn < 8; jn++)
#pragma unroll
                for (int h = 0; h < 2; h++)
#pragma unroll
                    for (int e = 0; e < 2; e++) {
                        const int col = wn * 64 + jn * 8 + 2 * t4 + e;
                        const float y = acc[im][jn][h * 2 + e] + smf[col];
                        acc[im][jn][h * 2 + e] = y;
                        sums[im][h] += y; ssqs[im][h] += y * y;
                    }
#pragma unroll
        for (int im = 0; im < NIM; im++)
#pragma unroll
            for (int h = 0; h < 2; h++) {
                sums[im][h] += __shfl_xor_sync(0xffffffffu, sums[im][h], 1);
                sums[im][h] += __shfl_xor_sync(0xffffffffu, sums[im][h], 2);
                ssqs[im][h] += __shfl_xor_sync(0xffffffffu, ssqs[im][h], 1);
                ssqs[im][h] += __shfl_xor_sync(0xffffffffu, ssqs[im][h], 2);
            }
        if (t4 == 0) {
#pragma unroll
            for (int im = 0; im < NIM; im++)
#pragma unroll
                for (int h = 0; h < 2; h++) {
                    const int row = wm * (16 * NIM) + im * 16 + g + 8 * h;
                    smred[wn * (ROWS * 2) + row * 2]     = sums[im][h];
                    smred[wn * (ROWS * 2) + row * 2 + 1] = ssqs[im][h];
                }
        }
        __syncthreads();
        if (tid < ROWS) {
            float s = 0.f, q = 0.f;
#pragma unroll
            for (int w = 0; w < 4; w++) {
                s += smred[w * (ROWS * 2) + tid * 2];
                q += smred[w * (ROWS * 2) + tid * 2 + 1];
            }
            const float mu = s * (1.f / 256.f);
            const float var = q * (1.f / 256.f) - mu * mu;
            smst[tid * 2]     = mu;
            smst[tid * 2 + 1] = rsqrtf(var + 1e-5f);
        }
        __syncthreads();

        float z2[NIM][2];
#pragma unroll
        for (int im = 0; im < NIM; im++)
#pragma unroll
            for (int h = 0; h < 2; h++) z2[im][h] = 0.f;
#pragma unroll
        for (int im = 0; im < NIM; im++)
#pragma unroll
            for (int h = 0; h < 2; h++) {
                const int row = wm * (16 * NIM) + im * 16 + g + 8 * h;
                const float mu = smst[row * 2], rstd = smst[row * 2 + 1];
                const long zrow = ((long)(row0 + row) * 4 + md) * 256;
#pragma unroll
                for (int jn = 0; jn < 8; jn++) {
                    const int c0 = wn * 64 + jn * 8 + 2 * t4;
                    const float z0 = (acc[im][jn][h * 2]     - mu) * rstd * smf[256 + c0]     + smf[512 + c0];
                    const float z1 = (acc[im][jn][h * 2 + 1] - mu) * rstd * smf[256 + c0 + 1] + smf[512 + c0 + 1];
                    z2[im][h] += z0 * z0 + z1 * z1;
                    __nv_bfloat16 h0, l0, h1, l1;
                    split2(z0, h0, l0); split2(z1, h1, l1);
                    *(uint32_t*)(g_Zhi + zrow + c0) = pack2(h0, h1);
                    *(uint32_t*)(g_Zlo + zrow + c0) = pack2(l0, l1);
                }
            }
#pragma unroll
        for (int im = 0; im < NIM; im++)
#pragma unroll
            for (int h = 0; h < 2; h++) {
                z2[im][h] += __shfl_xor_sync(0xffffffffu, z2[im][h], 1);
                z2[im][h] += __shfl_xor_sync(0xffffffffu, z2[im][h], 2);
            }
        __syncthreads();
        if (t4 == 0) {
#pragma unroll
            for (int im = 0; im < NIM; im++)
#pragma unroll
                for (int h = 0; h < 2; h++) {
                    const int row = wm * (16 * NIM) + im * 16 + g + 8 * h;
                    smred[wn * (ROWS * 2) + row * 2] = z2[im][h];
                }
        }
        __syncthreads();
        if (tid < ROWS) {
            float n2 = 0.f;
#pragma unroll
            for (int w = 0; w < 4; w++) n2 += smred[w * (ROWS * 2) + tid * 2];
            g_rnorm[((long)(row0 + tid) * 4 + md)] = 1.f / (sqrtf(n2) + 1e-6f);
        }
    } else {
        // head: col pair (even,odd) = (Z.Un_cg, Z.O_cg); softmax over m via
        // shfl xor 4,8 (modality m = g&3 lives in lane bits 2..3).
#pragma unroll
        for (int im = 0; im < NIM; im++)
#pragma unroll
            for (int h = 0; h < 2; h++) {
                const long grow = row0 + wm * (16 * NIM) + im * 16 + g + 8 * h;
                const float rs = g_rnorm[grow] * INVTAU;
#pragma unroll
                for (int jn = 0; jn < 8; jn++) {
                    const float s = acc[im][jn][h * 2] * rs;
                    const float o = acc[im][jn][h * 2 + 1];
                    float mx = s;
                    mx = fmaxf(mx, __shfl_xor_sync(0xffffffffu, mx, 4));
                    mx = fmaxf(mx, __shfl_xor_sync(0xffffffffu, mx, 8));
                    const float e = __expf(s - mx);
                    float tt = e + __shfl_xor_sync(0xffffffffu, e, 4);
                    tt += __shfl_xor_sync(0xffffffffu, tt, 8);
                    const float rr = e / tt;
                    const float ct = o * rr;
                    float lg = ct + __shfl_xor_sync(0xffffffffu, ct, 4);
                    lg += __shfl_xor_sync(0xffffffffu, lg, 8);
                    const int cg = blockIdx.x * 128 + wn * 32 + jn * 4 + t4;
                    const long obase = grow * 512 + cg;
                    out_sim[obase]     = s;
                    out_r[obase]       = rr;
                    out_contrib[obase] = ct;
                    if ((grow & 3) == 0)
                        out_logits[(grow >> 2) * 512 + cg] = lg + __ldg(cls + cg);
                }
            }
    }
}

// ---------------------------------------------------------------------------
// fp32 -> bf16 hi/lo conversion for f_* and W_*
// ---------------------------------------------------------------------------
__global__ void __launch_bounds__(256) cvt_fw(
    const float* f0, const float* f1, const float* f2, const float* f3,
    const float* w0, const float* w1, const float* w2, const float* w3)
{
    const int cum[8] = {2048, 4096, 5120, 5632, 5888, 6144, 6272, 6336};
    int blk = blockIdx.x, seg = 0;
    while (blk >= cum[seg]) seg++;
    int lb = blk - (seg ? cum[seg - 1] : 0);
    const float* src;
    __nv_bfloat16 *hi, *lo;
    switch (seg) {
        case 0: src = f0; hi = g_fhi;           lo = g_flo;           break;
        case 1: src = f1; hi = g_fhi + 2097152; lo = g_flo + 2097152; break;
        case 2: src = f2; hi = g_fhi + 4194304; lo = g_flo + 4194304; break;
        case 3: src = f3; hi = g_fhi + 5242880; lo = g_flo + 5242880; break;
        case 4: src = w0; hi = g_whi;           lo = g_wlo;           break;
        case 5: src = w1; hi = g_whi + 262144;  lo = g_wlo + 262144;  break;
        case 6: src = w2; hi = g_whi + 524288;  lo = g_wlo + 524288;  break;
        default:src = w3; hi = g_whi + 655360;  lo = g_wlo + 655360;  break;
    }
    long base = (long)lb * 1024 + threadIdx.x * 4;
    float4 v = *(const float4*)(src + base);
    __nv_bfloat16 h0, h1, h2, h3, l0, l1, l2, l3;
    split2(v.x, h0, l0); split2(v.y, h1, l1);
    split2(v.z, h2, l2); split2(v.w, h3, l3);
    *(__nv_bfloat162*)(hi + base)     = __halves2bfloat162(h0, h1);
    *(__nv_bfloat162*)(hi + base + 2) = __halves2bfloat162(h2, h3);
    *(__nv_bfloat162*)(lo + base)     = __halves2bfloat162(l0, l1);
    *(__nv_bfloat162*)(lo + base + 2) = __halves2bfloat162(l2, l3);
}

// ---------------------------------------------------------------------------
// Bcat rows interleaved: row 2c = l2norm(U)_c, row 2c+1 = O_c  -> bf16 hi/lo
// ---------------------------------------------------------------------------
__global__ void __launch_bounds__(256) normcat_kernel(const float* __restrict__ U,
                                                      const float* __restrict__ O)
{
    const int rr = blockIdx.x, t = threadIdx.x;
    const int c = rr >> 1, kind = rr & 1;
    __shared__ float ws[8];
    float v;
    if (kind == 0) {
        float u = U[(long)c * DD + t];
        float q = u * u;
#pragma unroll
        for (int o = 16; o > 0; o >>= 1) q += __shfl_xor_sync(0xffffffffu, q, o);
        if ((t & 31) == 0) ws[t >> 5] = q;
        __syncthreads();
        float n2 = 0.f;
#pragma unroll
        for (int i = 0; i < 8; i++) n2 += ws[i];
        v = u / (sqrtf(n2) + 1e-6f);
    } else {
        v = O[(long)c * DD + t];
    }
    __nv_bfloat16 h, l; split2(v, h, l);
    g_Bhi[(long)rr * DD + t] = h;
    g_Blo[(long)rr * DD + t] = l;
}

// ---------------------------------------------------------------------------
extern "C" void kernel_launch(void* const* d_in, const int* in_sizes, int n_in,
                              void* d_out, int out_size)
{
    const float *f[4], *W[4], *bi[4], *ga[4], *be[4];
    if (in_sizes[1] == 256 * 1024) {   // dict order: (f,W,b,g,be) per modality
        for (int m = 0; m < 4; m++) {
            f[m]  = (const float*)d_in[m * 5 + 0];
            W[m]  = (const float*)d_in[m * 5 + 1];
            bi[m] = (const float*)d_in[m * 5 + 2];
            ga[m] = (const float*)d_in[m * 5 + 3];
            be[m] = (const float*)d_in[m * 5 + 4];
        }
    } else {                            // signature order
        for (int m = 0; m < 4; m++) f[m] = (const float*)d_in[m];
        for (int m = 0; m < 4; m++) {
            W[m]  = (const float*)d_in[4 + m * 4 + 0];
            bi[m] = (const float*)d_in[4 + m * 4 + 1];
            ga[m] = (const float*)d_in[4 + m * 4 + 2];
            be[m] = (const float*)d_in[4 + m * 4 + 3];
        }
    }
    const float* U   = (const float*)d_in[20];
    const float* O   = (const float*)d_in[21];
    const float* cls = (const float*)d_in[22];

    float* out         = (float*)d_out;
    float* out_logits  = out;
    float* out_r       = out + (long)BB * CC;
    float* out_sim     = out_r + (long)NROW * CC;
    float* out_contrib = out_sim + (long)NROW * CC;

    cudaFuncSetAttribute(gemm_fused<1>, cudaFuncAttributeMaxDynamicSharedMemorySize, SMEM1);
    cudaFuncSetAttribute(gemm_fused<2>, cudaFuncAttributeMaxDynamicSharedMemorySize, SMEM2);

    cvt_fw<<<6336, 256>>>(f[0], f[1], f[2], f[3], W[0], W[1], W[2], W[3]);
    normcat_kernel<<<1024, 256>>>(U, O);

    // projections + fused LayerNorm/l2: 32-row CTAs -> 256 CTAs (fills SMs)
    gemm_fused<1><<<dim3(1, 64, 4), 256, SMEM1>>>(
        0, bi[0], bi[1], bi[2], bi[3], ga[0], ga[1], ga[2], ga[3],
        be[0], be[1], be[2], be[3], nullptr, nullptr, nullptr, nullptr, nullptr);

    // head GEMM + fused softmax/finalize: unchanged round-10 config (control)
    gemm_fused<2><<<dim3(4, 128, 1), 256, SMEM2>>>(
        1, nullptr, nullptr, nullptr, nullptr, nullptr, nullptr, nullptr, nullptr,
        nullptr, nullptr, nullptr, nullptr, cls, out_logits, out_r, out_sim, out_contrib);
}

// round 13
// speedup vs baseline: 1.8335x; 1.0521x over previous
#include <cuda_runtime.h>
#include <cuda_bf16.h>
#include <math.h>
#include <stdint.h>

#define BB 2048
#define DD 256
#define CC 512
#define NROW 8192
#define INVTAU (1.0f/0.07f)
#define FTOT 5767168   // 2048*(1024+1024+512+256)
#define WTOT 720896    // 256*(1024+1024+512+256)

// ---------------- scratch (no allocations allowed) ----------------
__device__ __nv_bfloat16 g_fhi[FTOT], g_flo[FTOT];
__device__ __nv_bfloat16 g_whi[WTOT], g_wlo[WTOT];
__device__ __nv_bfloat16 g_Zhi[NROW * DD], g_Zlo[NROW * DD];
__device__ __nv_bfloat16 g_Bhi[1024 * DD], g_Blo[1024 * DD]; // interleaved rows: 2c=Un_c, 2c+1=O_c
__device__ float         g_rnorm[NROW];

#define MMA_BF16(d, a, b) asm volatile( \
    "mma.sync.aligned.m16n8k16.row.col.f32.bf16.bf16.f32 " \
    "{%0,%1,%2,%3}, {%4,%5,%6,%7}, {%8,%9}, {%0,%1,%2,%3};\n" \
    : "+f"((d)[0]), "+f"((d)[1]), "+f"((d)[2]), "+f"((d)[3]) \
    : "r"((a)[0]), "r"((a)[1]), "r"((a)[2]), "r"((a)[3]), "r"((b)[0]), "r"((b)[1]))

#define LDM4(r, addr) asm volatile( \
    "ldmatrix.sync.aligned.m8n8.x4.shared.b16 {%0,%1,%2,%3}, [%4];" \
    : "=r"((r)[0]), "=r"((r)[1]), "=r"((r)[2]), "=r"((r)[3]) : "r"(addr))

#define CP16(dst, src) asm volatile("cp.async.cg.shared.global [%0], [%1], 16;" :: "r"(dst), "l"(src))
#define CP_COMMIT()    asm volatile("cp.async.commit_group;" ::: "memory")
#define CP_WAIT0()     asm volatile("cp.async.wait_group 0;" ::: "memory")
#define CP_WAIT1()     asm volatile("cp.async.wait_group 1;" ::: "memory")

__device__ __forceinline__ uint32_t smem_u32(const void* p) {
    uint32_t a;
    asm("{ .reg .u64 t; cvta.to.shared.u64 t, %1; cvt.u32.u64 %0, t; }" : "=r"(a) : "l"(p));
    return a;
}
__device__ __forceinline__ void split2(float x, __nv_bfloat16& h, __nv_bfloat16& l) {
    h = __float2bfloat16_rn(x);
    l = __float2bfloat16_rn(x - __bfloat162float(h));
}
__device__ __forceinline__ uint32_t pack2(__nv_bfloat16 a, __nv_bfloat16 b) {
    __nv_bfloat162 t = __halves2bfloat162(a, b);
    return *(uint32_t*)&t;
}

// smem layout header:
//  [0]     params: bias|gamma|beta (768 f)          3072 B
//  [3072]  smred: 4 warp-cols x ROWS x 2           <=2048 B
//  [5120]  stats: ROWS x 2 (mu,rstd)                <=512 B
//  [5632]  tiles: 2 stages
//  stage: Ahi 0 | Alo A_ARR | Bhi 2*A_ARR | Blo 2*A_ARR+B_ARR  (80 B/row)
#define SM_PARAM 0
#define SM_RED   3072
#define SM_STAT  5120
#define SM_T     5632
#define SMEM_PROJ (SM_T + 2 * (2 * 32 * 80 + 2 * 256 * 80))   // 97792
#define SMEM_HEAD (SM_T + 2 * (2 * 64 * 80 + 2 * 128 * 80))   // 67072

// issue cp.async for one K32 stage: A ROWS rows, B NCOL rows, hi+lo (256 thr)
template<int NIM, int NCOL>
__device__ __forceinline__ void load_stage_async(
    uint32_t tile_sm, const __nv_bfloat16* Ah, const __nv_bfloat16* Al,
    const __nv_bfloat16* Bh, const __nv_bfloat16* Bl,
    int lda, int ldb, int k0, int tid)
{
    constexpr int ROWS  = 32 * NIM;
    constexpr int A_ARR = ROWS * 80;
    constexpr int B_ARR = NCOL * 80;
#pragma unroll
    for (int i = 0; i < NIM; i++) {   // A: 2 arrays x ROWS*4 uint4
        const int n = tid + (i << 8);
        const int a = n / (ROWS * 4), idx = n % (ROWS * 4);
        const int row = idx >> 2, ch = idx & 3;
        const __nv_bfloat16* src = a ? Al : Ah;
        const char* gsrc = (const char*)(src + (long)row * lda + k0 + (ch << 3));
        CP16(tile_sm + a * A_ARR + row * 80 + (ch << 4), gsrc);
    }
#pragma unroll
    for (int i = 0; i < NCOL / 32; i++) {   // B: 2 arrays x NCOL*4 uint4
        const int m = tid + (i << 8);
        const int a = m / (NCOL * 4), idx = m % (NCOL * 4);
        const int row = idx >> 2, ch = idx & 3;
        const __nv_bfloat16* src = a ? Bl : Bh;
        const char* gsrc = (const char*)(src + (long)row * ldb + k0 + (ch << 3));
        CP16(tile_sm + 2 * A_ARR + a * B_ARR + row * 80 + (ch << 4), gsrc);
    }
    CP_COMMIT();
}

// ---------------------------------------------------------------------------
// CTA tile (32*NIM) rows x NCOL cols, 256 threads, warp grid 2x4
// (warp tile 16*NIM x NCOL/4), ldmatrix + cp.async double buffer.
//   proj: <1,256,2> mode 0, grid (1, 64, 4)   [256 CTAs, 2/SM]
//   head: <2,128,3> mode 1, grid (8, 128, 1)  [1024 CTAs, 3/SM]
// ---------------------------------------------------------------------------
template<int NIM, int NCOL, int MINB>
__global__ void __launch_bounds__(256, MINB) gemm_fused(
    int mode,
    const float* b0, const float* b1, const float* b2, const float* b3,
    const float* G0, const float* G1, const float* G2, const float* G3,
    const float* e0, const float* e1, const float* e2, const float* e3,
    const float* cls, float* out_logits, float* out_r,
    float* out_sim, float* out_contrib)
{
    constexpr int ROWS    = 32 * NIM;
    constexpr int A_ARR   = ROWS * 80;
    constexpr int B_ARR   = NCOL * 80;
    constexpr int STAGE_B = 2 * A_ARR + 2 * B_ARR;
    constexpr int NJJ     = NCOL / 64;    // 16-row B groups per warp per k16
    constexpr int WCOL    = NCOL / 4;     // warp tile cols

    extern __shared__ char smem[];
    const uint32_t sbase = smem_u32(smem);
    const int tid = threadIdx.x, wid = tid >> 5, lane = tid & 31;
    float* smf   = (float*)(smem + SM_PARAM);
    float* smred = (float*)(smem + SM_RED);
    float* smst  = (float*)(smem + SM_STAT);

    const int md = (mode == 0) ? blockIdx.z : 0;
    if (mode == 0) {
        const float* bp = md == 0 ? b0 : md == 1 ? b1 : md == 2 ? b2 : b3;
        const float* gp = md == 0 ? G0 : md == 1 ? G1 : md == 2 ? G2 : G3;
        const float* ep = md == 0 ? e0 : md == 1 ? e1 : md == 2 ? e2 : e3;
        smf[tid] = bp[tid]; smf[256 + tid] = gp[tid]; smf[512 + tid] = ep[tid];
    }
    __syncthreads();

    // operand pointers
    const __nv_bfloat16 *Ah, *Al, *Bh, *Bl;
    int lda, ldb, K;
    const int row0 = blockIdx.y * ROWS;
    if (mode == 0) {
        const long foff[4] = {0, 2097152, 4194304, 5242880};
        const long woff[4] = {0, 262144, 524288, 655360};
        const int  Km[4]   = {1024, 1024, 512, 256};
        K = Km[md];
        Ah = g_fhi + foff[md] + (long)row0 * K;
        Al = g_flo + foff[md] + (long)row0 * K;
        Bh = g_whi + woff[md];
        Bl = g_wlo + woff[md];
        lda = ldb = K;
    } else {
        K = DD;
        Ah = g_Zhi + (long)row0 * DD;
        Al = g_Zlo + (long)row0 * DD;
        Bh = g_Bhi + (long)blockIdx.x * NCOL * DD;
        Bl = g_Blo + (long)blockIdx.x * NCOL * DD;
        lda = ldb = DD;
    }
    const int nkt = K >> 5;

    const int wm = wid >> 2, wn = wid & 3;    // 2x4 warp grid
    const int g = lane >> 2, t4 = lane & 3;

    uint32_t aoff[NIM];
#pragma unroll
    for (int im = 0; im < NIM; im++)
        aoff[im] = ((wm * (16 * NIM) + im * 16 + (lane & 15)) * 40
                    + ((lane >> 4) << 3)) * 2;
    const uint32_t boff = ((wn * WCOL + (lane & 7) + ((lane >> 4) << 3)) * 40
                           + (((lane >> 3) & 1) << 3)) * 2;

    float acc[NIM][2 * NJJ][4];
#pragma unroll
    for (int im = 0; im < NIM; im++)
#pragma unroll
        for (int jn = 0; jn < 2 * NJJ; jn++)
#pragma unroll
            for (int q = 0; q < 4; q++) acc[im][jn][q] = 0.f;

    // ---------------- cp.async double-buffered mainloop ----------------
    load_stage_async<NIM, NCOL>(sbase + SM_T, Ah, Al, Bh, Bl, lda, ldb, 0, tid);
    for (int kt = 0; kt < nkt; kt++) {
        const bool hasNext = (kt + 1 < nkt);
        if (hasNext)
            load_stage_async<NIM, NCOL>(sbase + SM_T + ((kt + 1) & 1) * STAGE_B,
                                        Ah, Al, Bh, Bl, lda, ldb, (kt + 1) << 5, tid);
        if (hasNext) CP_WAIT1(); else CP_WAIT0();
        __syncthreads();

        const uint32_t sst = sbase + SM_T + (kt & 1) * STAGE_B;
#pragma unroll
        for (int ks = 0; ks < 64; ks += 32) {   // one k16 step = 32 B
            uint32_t ah[NIM][4], al[NIM][4];
#pragma unroll
            for (int im = 0; im < NIM; im++) {
                LDM4(ah[im], sst + aoff[im] + ks);
                LDM4(al[im], sst + A_ARR + aoff[im] + ks);
            }
#pragma unroll
            for (int jj = 0; jj < NJJ; jj++) {
                uint32_t bh[4], bl[4];
                LDM4(bh, sst + 2 * A_ARR + boff + jj * 1280 + ks);
                LDM4(bl, sst + 2 * A_ARR + B_ARR + boff + jj * 1280 + ks);
#pragma unroll
                for (int im = 0; im < NIM; im++) {
                    MMA_BF16(acc[im][2 * jj],     ah[im], &bh[0]);
                    MMA_BF16(acc[im][2 * jj],     ah[im], &bl[0]);
                    MMA_BF16(acc[im][2 * jj],     al[im], &bh[0]);
                    MMA_BF16(acc[im][2 * jj + 1], ah[im], &bh[2]);
                    MMA_BF16(acc[im][2 * jj + 1], ah[im], &bl[2]);
                    MMA_BF16(acc[im][2 * jj + 1], al[im], &bh[2]);
                }
            }
        }
        __syncthreads();
    }

    // ---------------- fused register epilogue ----------------
    // thread rows: wm*(16*NIM) + im*16 + g + 8h   cols: wn*WCOL + jn*8 + 2*t4 + e
    if (mode == 0) {
        float sums[NIM][2], ssqs[NIM][2];
#pragma unroll
        for (int im = 0; im < NIM; im++)
#pragma unroll
            for (int h = 0; h < 2; h++) { sums[im][h] = 0.f; ssqs[im][h] = 0.f; }
#pragma unroll
        for (int im = 0; im < NIM; im++)
#pragma unroll
            for (int jn = 0; jn < 2 * NJJ; jn++)
#pragma unroll
                for (int h = 0; h < 2; h++)
#pragma unroll
                    for (int e = 0; e < 2; e++) {
                        const int col = wn * WCOL + jn * 8 + 2 * t4 + e;
                        const float y = acc[im][jn][h * 2 + e] + smf[col];
                        acc[im][jn][h * 2 + e] = y;
                        sums[im][h] += y; ssqs[im][h] += y * y;
                    }
#pragma unroll
        for (int im = 0; im < NIM; im++)
#pragma unroll
            for (int h = 0; h < 2; h++) {
                sums[im][h] += __shfl_xor_sync(0xffffffffu, sums[im][h], 1);
                sums[im][h] += __shfl_xor_sync(0xffffffffu, sums[im][h], 2);
                ssqs[im][h] += __shfl_xor_sync(0xffffffffu, ssqs[im][h], 1);
                ssqs[im][h] += __shfl_xor_sync(0xffffffffu, ssqs[im][h], 2);
            }
        if (t4 == 0) {
#pragma unroll
            for (int im = 0; im < NIM; im++)
#pragma unroll
                for (int h = 0; h < 2; h++) {
                    const int row = wm * (16 * NIM) + im * 16 + g + 8 * h;
                    smred[wn * (ROWS * 2) + row * 2]     = sums[im][h];
                    smred[wn * (ROWS * 2) + row * 2 + 1] = ssqs[im][h];
                }
        }
        __syncthreads();
        if (tid < ROWS) {
            float s = 0.f, q = 0.f;
#pragma unroll
            for (int w = 0; w < 4; w++) {
                s += smred[w * (ROWS * 2) + tid * 2];
                q += smred[w * (ROWS * 2) + tid * 2 + 1];
            }
            const float mu = s * (1.f / 256.f);
            const float var = q * (1.f / 256.f) - mu * mu;
            smst[tid * 2]     = mu;
            smst[tid * 2 + 1] = rsqrtf(var + 1e-5f);
        }
        __syncthreads();

        float z2[NIM][2];
#pragma unroll
        for (int im = 0; im < NIM; im++)
#pragma unroll
            for (int h = 0; h < 2; h++) z2[im][h] = 0.f;
#pragma unroll
        for (int im = 0; im < NIM; im++)
#pragma unroll
            for (int h = 0; h < 2; h++) {
                const int row = wm * (16 * NIM) + im * 16 + g + 8 * h;
                const float mu = smst[row * 2], rstd = smst[row * 2 + 1];
                const long zrow = ((long)(row0 + row) * 4 + md) * 256;
#pragma unroll
                for (int jn = 0; jn < 2 * NJJ; jn++) {
                    const int c0 = wn * WCOL + jn * 8 + 2 * t4;
                    const float z0 = (acc[im][jn][h * 2]     - mu) * rstd * smf[256 + c0]     + smf[512 + c0];
                    const float z1 = (acc[im][jn][h * 2 + 1] - mu) * rstd * smf[256 + c0 + 1] + smf[512 + c0 + 1];
                    z2[im][h] += z0 * z0 + z1 * z1;
                    __nv_bfloat16 h0, l0, h1, l1;
                    split2(z0, h0, l0); split2(z1, h1, l1);
                    *(uint32_t*)(g_Zhi + zrow + c0) = pack2(h0, h1);
                    *(uint32_t*)(g_Zlo + zrow + c0) = pack2(l0, l1);
                }
            }
#pragma unroll
        for (int im = 0; im < NIM; im++)
#pragma unroll
            for (int h = 0; h < 2; h++) {
                z2[im][h] += __shfl_xor_sync(0xffffffffu, z2[im][h], 1);
                z2[im][h] += __shfl_xor_sync(0xffffffffu, z2[im][h], 2);
            }
        __syncthreads();
        if (t4 == 0) {
#pragma unroll
            for (int im = 0; im < NIM; im++)
#pragma unroll
                for (int h = 0; h < 2; h++) {
                    const int row = wm * (16 * NIM) + im * 16 + g + 8 * h;
                    smred[wn * (ROWS * 2) + row * 2] = z2[im][h];
                }
        }
        __syncthreads();
        if (tid < ROWS) {
            float n2 = 0.f;
#pragma unroll
            for (int w = 0; w < 4; w++) n2 += smred[w * (ROWS * 2) + tid * 2];
            g_rnorm[((long)(row0 + tid) * 4 + md)] = 1.f / (sqrtf(n2) + 1e-6f);
        }
    } else {
        // head: col pair (even,odd) = (Z.Un_cg, Z.O_cg); softmax over m via
        // shfl xor 4,8 (modality m = g&3 lives in lane bits 2..3).
#pragma unroll
        for (int im = 0; im < NIM; im++)
#pragma unroll
            for (int h = 0; h < 2; h++) {
                const long grow = row0 + wm * (16 * NIM) + im * 16 + g + 8 * h;
                const float rs = g_rnorm[grow] * INVTAU;
#pragma unroll
                for (int jn = 0; jn < 2 * NJJ; jn++) {
                    const float s = acc[im][jn][h * 2] * rs;
                    const float o = acc[im][jn][h * 2 + 1];
                    float mx = s;
                    mx = fmaxf(mx, __shfl_xor_sync(0xffffffffu, mx, 4));
                    mx = fmaxf(mx, __shfl_xor_sync(0xffffffffu, mx, 8));
                    const float e = __expf(s - mx);
                    float tt = e + __shfl_xor_sync(0xffffffffu, e, 4);
                    tt += __shfl_xor_sync(0xffffffffu, tt, 8);
                    const float rr = e / tt;
                    const float ct = o * rr;
                    float lg = ct + __shfl_xor_sync(0xffffffffu, ct, 4);
                    lg += __shfl_xor_sync(0xffffffffu, lg, 8);
                    const int cg = blockIdx.x * (NCOL / 2) + wn * (NCOL / 8) + jn * 4 + t4;
                    const long obase = grow * 512 + cg;
                    out_sim[obase]     = s;
                    out_r[obase]       = rr;
                    out_contrib[obase] = ct;
                    if ((grow & 3) == 0)
                        out_logits[(grow >> 2) * 512 + cg] = lg + __ldg(cls + cg);
                }
            }
    }
}

// ---------------------------------------------------------------------------
// fp32 -> bf16 hi/lo conversion for f_* and W_*
// ---------------------------------------------------------------------------
__global__ void __launch_bounds__(256) cvt_fw(
    const float* f0, const float* f1, const float* f2, const float* f3,
    const float* w0, const float* w1, const float* w2, const float* w3)
{
    const int cum[8] = {2048, 4096, 5120, 5632, 5888, 6144, 6272, 6336};
    int blk = blockIdx.x, seg = 0;
    while (blk >= cum[seg]) seg++;
    int lb = blk - (seg ? cum[seg - 1] : 0);
    const float* src;
    __nv_bfloat16 *hi, *lo;
    switch (seg) {
        case 0: src = f0; hi = g_fhi;           lo = g_flo;           break;
        case 1: src = f1; hi = g_fhi + 2097152; lo = g_flo + 2097152; break;
        case 2: src = f2; hi = g_fhi + 4194304; lo = g_flo + 4194304; break;
        case 3: src = f3; hi = g_fhi + 5242880; lo = g_flo + 5242880; break;
        case 4: src = w0; hi = g_whi;           lo = g_wlo;           break;
        case 5: src = w1; hi = g_whi + 262144;  lo = g_wlo + 262144;  break;
        case 6: src = w2; hi = g_whi + 524288;  lo = g_wlo + 524288;  break;
        default:src = w3; hi = g_whi + 655360;  lo = g_wlo + 655360;  break;
    }
    long base = (long)lb * 1024 + threadIdx.x * 4;
    float4 v = *(const float4*)(src + base);
    __nv_bfloat16 h0, h1, h2, h3, l0, l1, l2, l3;
    split2(v.x, h0, l0); split2(v.y, h1, l1);
    split2(v.z, h2, l2); split2(v.w, h3, l3);
    *(__nv_bfloat162*)(hi + base)     = __halves2bfloat162(h0, h1);
    *(__nv_bfloat162*)(hi + base + 2) = __halves2bfloat162(h2, h3);
    *(__nv_bfloat162*)(lo + base)     = __halves2bfloat162(l0, l1);
    *(__nv_bfloat162*)(lo + base + 2) = __halves2bfloat162(l2, l3);
}

// ---------------------------------------------------------------------------
// Bcat rows interleaved: row 2c = l2norm(U)_c, row 2c+1 = O_c  -> bf16 hi/lo
// ---------------------------------------------------------------------------
__global__ void __launch_bounds__(256) normcat_kernel(const float* __restrict__ U,
                                                      const float* __restrict__ O)
{
    const int rr = blockIdx.x, t = threadIdx.x;
    const int c = rr >> 1, kind = rr & 1;
    __shared__ float ws[8];
    float v;
    if (kind == 0) {
        float u = U[(long)c * DD + t];
        float q = u * u;
#pragma unroll
        for (int o = 16; o > 0; o >>= 1) q += __shfl_xor_sync(0xffffffffu, q, o);
        if ((t & 31) == 0) ws[t >> 5] = q;
        __syncthreads();
        float n2 = 0.f;
#pragma unroll
        for (int i = 0; i < 8; i++) n2 += ws[i];
        v = u / (sqrtf(n2) + 1e-6f);
    } else {
        v = O[(long)c * DD + t];
    }
    __nv_bfloat16 h, l; split2(v, h, l);
    g_Bhi[(long)rr * DD + t] = h;
    g_Blo[(long)rr * DD + t] = l;
}

// ---------------------------------------------------------------------------
extern "C" void kernel_launch(void* const* d_in, const int* in_sizes, int n_in,
                              void* d_out, int out_size)
{
    const float *f[4], *W[4], *bi[4], *ga[4], *be[4];
    if (in_sizes[1] == 256 * 1024) {   // dict order: (f,W,b,g,be) per modality
        for (int m = 0; m < 4; m++) {
            f[m]  = (const float*)d_in[m * 5 + 0];
            W[m]  = (const float*)d_in[m * 5 + 1];
            bi[m] = (const float*)d_in[m * 5 + 2];
            ga[m] = (const float*)d_in[m * 5 + 3];
            be[m] = (const float*)d_in[m * 5 + 4];
        }
    } else {                            // signature order
        for (int m = 0; m < 4; m++) f[m] = (const float*)d_in[m];
        for (int m = 0; m < 4; m++) {
            W[m]  = (const float*)d_in[4 + m * 4 + 0];
            bi[m] = (const float*)d_in[4 + m * 4 + 1];
            ga[m] = (const float*)d_in[4 + m * 4 + 2];
            be[m] = (const float*)d_in[4 + m * 4 + 3];
        }
    }
    const float* U   = (const float*)d_in[20];
    const float* O   = (const float*)d_in[21];
    const float* cls = (const float*)d_in[22];

    float* out         = (float*)d_out;
    float* out_logits  = out;
    float* out_r       = out + (long)BB * CC;
    float* out_sim     = out_r + (long)NROW * CC;
    float* out_contrib = out_sim + (long)NROW * CC;

    cudaFuncSetAttribute((const void*)gemm_fused<1, 256, 2>,
                         cudaFuncAttributeMaxDynamicSharedMemorySize, SMEM_PROJ);
    cudaFuncSetAttribute((const void*)gemm_fused<2, 128, 3>,
                         cudaFuncAttributeMaxDynamicSharedMemorySize, SMEM_HEAD);

    cvt_fw<<<6336, 256>>>(f[0], f[1], f[2], f[3], W[0], W[1], W[2], W[3]);
    normcat_kernel<<<1024, 256>>>(U, O);

    // projections + fused LayerNorm/l2: 32-row x 256-col CTAs (control)
    gemm_fused<1, 256, 2><<<dim3(1, 64, 4), 256, SMEM_PROJ>>>(
        0, bi[0], bi[1], bi[2], bi[3], ga[0], ga[1], ga[2], ga[3],
        be[0], be[1], be[2], be[3], nullptr, nullptr, nullptr, nullptr, nullptr);

    // head GEMM + fused softmax/finalize: 64-row x 128-col CTAs, 3/SM
    gemm_fused<2, 128, 3><<<dim3(8, 128, 1), 256, SMEM_HEAD>>>(
        1, nullptr, nullptr, nullptr, nullptr, nullptr, nullptr, nullptr, nullptr,
        nullptr, nullptr, nullptr, nullptr, cls, out_logits, out_r, out_sim, out_contrib);
}